// round 9
// baseline (speedup 1.0000x reference)
#include <cuda_runtime.h>
#include <cuda_bf16.h>
#include <math.h>
#include <stdint.h>

#define BB 2
#define TT 2048
#define CC 1024
#define HH 16
#define DH 64

// ---------------------------------------------------------------------------
// Scratch (device globals: allocation-free rule)
// ---------------------------------------------------------------------------
__device__ float g_decay[HH * TT];                 // [h][dist]

__device__ __nv_bfloat16 g_q_h[4194304], g_q_l[4194304];   // [b][h][t][d]
__device__ __nv_bfloat16 g_k_h[4194304], g_k_l[4194304];   // [b][h][t][d]
__device__ __nv_bfloat16 g_v_h[4194304], g_v_l[4194304];   // [b][h][t][d]  (natural!)
__device__ __nv_bfloat16 g_ao_h[4194304], g_ao_l[4194304];

__device__ __nv_bfloat16 g_x_h[4194304],  g_x_l[4194304];
__device__ __nv_bfloat16 g_w1_h[3145728], g_w1_l[3145728];
__device__ __nv_bfloat16 g_w2_h[1048576], g_w2_l[1048576];

// ---------------------------------------------------------------------------
// helpers
// ---------------------------------------------------------------------------
__device__ __forceinline__ uint32_t smem_u32(const void* p) {
    uint32_t a;
    asm("{ .reg .u64 t; cvta.to.shared.u64 t, %1; cvt.u32.u64 %0, t; }" : "=r"(a) : "l"(p));
    return a;
}
__device__ __forceinline__ uint32_t swz(uint32_t off) {     // 128B rows
    return off ^ ((off >> 3) & 0x70);
}
__device__ __forceinline__ void ldmx4(uint32_t* r, uint32_t addr) {
    asm volatile("ldmatrix.sync.aligned.m8n8.x4.shared.b16 {%0,%1,%2,%3}, [%4];"
                 : "=r"(r[0]), "=r"(r[1]), "=r"(r[2]), "=r"(r[3]) : "r"(addr));
}
__device__ __forceinline__ void ldmx4t(uint32_t* r, uint32_t addr) {
    asm volatile("ldmatrix.sync.aligned.m8n8.x4.trans.shared.b16 {%0,%1,%2,%3}, [%4];"
                 : "=r"(r[0]), "=r"(r[1]), "=r"(r[2]), "=r"(r[3]) : "r"(addr));
}
__device__ __forceinline__ void mma_bf16(float* c, const uint32_t* a, uint32_t b0, uint32_t b1) {
    asm volatile("mma.sync.aligned.m16n8k16.row.col.f32.bf16.bf16.f32 "
                 "{%0,%1,%2,%3}, {%4,%5,%6,%7}, {%8,%9}, {%0,%1,%2,%3};"
                 : "+f"(c[0]), "+f"(c[1]), "+f"(c[2]), "+f"(c[3])
                 : "r"(a[0]), "r"(a[1]), "r"(a[2]), "r"(a[3]), "r"(b0), "r"(b1));
}
__device__ __forceinline__ void cpa16(uint32_t dst, const void* src) {
    asm volatile("cp.async.cg.shared.global [%0], [%1], 16;" :: "r"(dst), "l"(src));
}
#define CP_COMMIT() asm volatile("cp.async.commit_group;" ::: "memory")
#define CP_WAIT1()  asm volatile("cp.async.wait_group 1;" ::: "memory")
#define CP_WAIT0()  asm volatile("cp.async.wait_group 0;" ::: "memory")

// fast 2^y via FMA only (no MUFU)
__device__ __forceinline__ float fexp2(float y) {
    y = fminf(fmaxf(y, -120.f), 80.f);
    float z = y + 12582912.f;
    int iz = __float_as_int(z);
    float f = y - (z - 12582912.f);
    float p = 1.3333558e-3f;
    p = fmaf(p, f, 9.6181291e-3f);
    p = fmaf(p, f, 5.5504109e-2f);
    p = fmaf(p, f, 2.4022651e-1f);
    p = fmaf(p, f, 6.9314718e-1f);
    p = fmaf(p, f, 1.0f);
    return p * __int_as_float((iz + (127 - 0x4B400000)) << 23);
}
__device__ __forceinline__ uint32_t pack_hl(float x, float y, uint32_t& lo) {
    __nv_bfloat16 hx = __float2bfloat16(x), hy = __float2bfloat16(y);
    __nv_bfloat16 lx = __float2bfloat16(x - __bfloat162float(hx));
    __nv_bfloat16 ly = __float2bfloat16(y - __bfloat162float(hy));
    lo = ((uint32_t)__bfloat16_as_ushort(ly) << 16) | (uint32_t)__bfloat16_as_ushort(lx);
    return ((uint32_t)__bfloat16_as_ushort(hy) << 16) | (uint32_t)__bfloat16_as_ushort(hx);
}

// ---------------------------------------------------------------------------
__global__ void split_bf16(const float* __restrict__ src, __nv_bfloat16* __restrict__ hi,
                           __nv_bfloat16* __restrict__ lo, int n4) {
    int i = blockIdx.x * blockDim.x + threadIdx.x;
    if (i < n4) {
        float4 v = ((const float4*)src)[i];
        __nv_bfloat16 h0 = __float2bfloat16(v.x), h1 = __float2bfloat16(v.y);
        __nv_bfloat16 h2 = __float2bfloat16(v.z), h3 = __float2bfloat16(v.w);
        __nv_bfloat162* H = (__nv_bfloat162*)hi;
        __nv_bfloat162* L = (__nv_bfloat162*)lo;
        H[i * 2]     = __nv_bfloat162(h0, h1);
        H[i * 2 + 1] = __nv_bfloat162(h2, h3);
        L[i * 2]     = __nv_bfloat162(__float2bfloat16(v.x - __bfloat162float(h0)),
                                      __float2bfloat16(v.y - __bfloat162float(h1)));
        L[i * 2 + 1] = __nv_bfloat162(__float2bfloat16(v.z - __bfloat162float(h2)),
                                      __float2bfloat16(v.w - __bfloat162float(h3)));
    }
}

__global__ void decay_kernel(const float* __restrict__ lambda_raw) {
    int idx = blockIdx.x * blockDim.x + threadIdx.x;
    if (idx < HH * TT) {
        int h = idx / TT;
        int d = idx % TT;
        float lam = log1pf(expf(lambda_raw[h]));
        g_decay[idx] = expf(-lam * (float)d);
    }
}

// ---------------------------------------------------------------------------
// async tile loaders
// ---------------------------------------------------------------------------
__device__ __forceinline__ void gload_a256(const __nv_bfloat16* __restrict__ g,
                                           uint32_t dst, int tid) {
#pragma unroll
    for (int i = 0; i < 8; i++) {
        int slot = tid + i * 256;
        int row = slot >> 3;
        int c16 = slot & 7;
        cpa16(dst + swz(row * 128 + c16 * 16), g + (size_t)row * 1024 + c16 * 8);
    }
}
__device__ __forceinline__ void gload_b128(const __nv_bfloat16* __restrict__ g,
                                           uint32_t dst, int tid) {
#pragma unroll
    for (int i = 0; i < 4; i++) {
        int slot = tid + i * 256;
        int row = slot >> 3;
        int c16 = slot & 7;
        cpa16(dst + swz(row * 128 + c16 * 16), g + (size_t)row * 1024 + c16 * 8);
    }
}
__device__ __forceinline__ void gload_q256(const __nv_bfloat16* __restrict__ g,
                                           uint32_t dst, int tid) {
    // 256 rows x 64 bf16 contiguous (32KB = 2048 chunks; 8 per thread)
#pragma unroll
    for (int i = 0; i < 8; i++) {
        int slot = tid + i * 256;
        int row = slot >> 3;
        int c16 = slot & 7;
        cpa16(dst + swz(row * 128 + c16 * 16), g + (size_t)row * 64 + c16 * 8);
    }
}
__device__ __forceinline__ void gload_kv64(const __nv_bfloat16* __restrict__ g,
                                           uint32_t dst, int tid) {
    // 64 rows x 64 bf16 contiguous (8KB = 512 chunks; 2 per thread)
#pragma unroll
    for (int i = 0; i < 2; i++) {
        int slot = tid + i * 256;
        int row = slot >> 3;
        int c16 = slot & 7;
        cpa16(dst + swz(row * 128 + c16 * 16), g + (size_t)row * 64 + c16 * 8);
    }
}

// ---------------------------------------------------------------------------
// bf16x3 mma.sync NT GEMM, 256x128 CTA tile, BK=64, double-buffered.
// ---------------------------------------------------------------------------
#define GA_H 0
#define GA_L 32768
#define GB_H 65536
#define GB_L 81920
#define GBUF 98304
#define GEMM_SMEM 196608

template <int EPI>
__launch_bounds__(256, 1)
__global__ void gemm_mma(const __nv_bfloat16* __restrict__ Ah, const __nv_bfloat16* __restrict__ Al,
                         const __nv_bfloat16* __restrict__ Bh, const __nv_bfloat16* __restrict__ Bl,
                         const float* __restrict__ bias, float* __restrict__ Cout, int N) {
    extern __shared__ char smem[];
    const uint32_t sb = smem_u32(smem);
    const int tid = threadIdx.x;
    const int wid = tid >> 5;
    const int lane = tid & 31;
    const int wm = wid & 3;
    const int wn = wid >> 2;
    const int n0 = blockIdx.x * 128;
    const int m0 = blockIdx.y * 256;

    const int a_row = (lane & 7) + ((lane >> 3) & 1) * 8;
    const int a_kc  = lane >> 4;
    const int b_row = ((lane >> 4) * 8) + (lane & 7);
    const int b_kc  = (lane >> 3) & 1;

    const __nv_bfloat16* Abase_h = Ah + (size_t)m0 * 1024;
    const __nv_bfloat16* Abase_l = Al + (size_t)m0 * 1024;
    const __nv_bfloat16* Bbase_h = Bh + (size_t)n0 * 1024;
    const __nv_bfloat16* Bbase_l = Bl + (size_t)n0 * 1024;

    float acc[4][8][4];
#pragma unroll
    for (int i = 0; i < 4; i++)
#pragma unroll
        for (int j = 0; j < 8; j++)
#pragma unroll
            for (int q = 0; q < 4; q++) acc[i][j][q] = 0.f;

    gload_a256(Abase_h, sb + GA_H, tid);
    gload_a256(Abase_l, sb + GA_L, tid);
    gload_b128(Bbase_h, sb + GB_H, tid);
    gload_b128(Bbase_l, sb + GB_L, tid);
    CP_COMMIT();

    for (int c = 0; c < 16; c++) {
        const uint32_t cur = (c & 1) ? GBUF : 0u;
        const uint32_t nxt = cur ^ GBUF;
        if (c < 15) {
            const size_t ka = (size_t)(c + 1) * 64;
            gload_a256(Abase_h + ka, sb + nxt + GA_H, tid);
            gload_a256(Abase_l + ka, sb + nxt + GA_L, tid);
            gload_b128(Bbase_h + ka, sb + nxt + GB_H, tid);
            gload_b128(Bbase_l + ka, sb + nxt + GB_L, tid);
            CP_COMMIT();
            CP_WAIT1();
        } else {
            CP_WAIT0();
        }
        __syncthreads();

        const uint32_t sAh = sb + cur + GA_H, sAl = sb + cur + GA_L;
        const uint32_t sBh = sb + cur + GB_H, sBl = sb + cur + GB_L;
#pragma unroll
        for (int kt = 0; kt < 4; kt++) {
            uint32_t ah[4][4], al[4][4];
#pragma unroll
            for (int mi = 0; mi < 4; mi++) {
                uint32_t off = swz((wm * 64 + mi * 16 + a_row) * 128 + (kt * 2 + a_kc) * 16);
                ldmx4(ah[mi], sAh + off);
                ldmx4(al[mi], sAl + off);
            }
#pragma unroll
            for (int ng = 0; ng < 4; ng++) {
                uint32_t bh[4], bl[4];
                uint32_t off = swz((wn * 64 + ng * 16 + b_row) * 128 + (kt * 2 + b_kc) * 16);
                ldmx4(bh, sBh + off);
                ldmx4(bl, sBl + off);
#pragma unroll
                for (int mi = 0; mi < 4; mi++) {
                    mma_bf16(acc[mi][2 * ng],     ah[mi], bh[0], bh[1]);
                    mma_bf16(acc[mi][2 * ng],     al[mi], bh[0], bh[1]);
                    mma_bf16(acc[mi][2 * ng],     ah[mi], bl[0], bl[1]);
                    mma_bf16(acc[mi][2 * ng + 1], ah[mi], bh[2], bh[3]);
                    mma_bf16(acc[mi][2 * ng + 1], al[mi], bh[2], bh[3]);
                    mma_bf16(acc[mi][2 * ng + 1], ah[mi], bl[2], bl[3]);
                }
            }
        }
        __syncthreads();
    }

#pragma unroll
    for (int mi = 0; mi < 4; mi++) {
#pragma unroll
        for (int j = 0; j < 8; j++) {
            int row = m0 + wm * 64 + mi * 16 + (lane >> 2);
            int o = n0 + wn * 64 + j * 8 + (lane & 3) * 2;
            float b0 = bias[o], b1 = bias[o + 1];
#pragma unroll
            for (int half = 0; half < 2; half++) {
                int m = row + half * 8;
                float vx = acc[mi][j][half * 2] + b0;
                float vy = acc[mi][j][half * 2 + 1] + b1;
                if (EPI == 0) {
                    int s = o >> 10;
                    int rem = o & 1023;
                    int hh = rem >> 6;
                    int d = rem & 63;
                    int bb = m >> 11;
                    int t = m & 2047;
                    __nv_bfloat16 h0 = __float2bfloat16(vx);
                    __nv_bfloat16 l0 = __float2bfloat16(vx - __bfloat162float(h0));
                    __nv_bfloat16 h1 = __float2bfloat16(vy);
                    __nv_bfloat16 l1 = __float2bfloat16(vy - __bfloat162float(h1));
                    // Q, K, V all stored natural [b][h][t][d] (coalesced float2)
                    size_t idx = (((size_t)(bb * HH + hh) * TT + t) * DH + d) >> 1;
                    __nv_bfloat162 hv(h0, h1), lv(l0, l1);
                    if (s == 0)      { ((__nv_bfloat162*)g_q_h)[idx] = hv;
                                       ((__nv_bfloat162*)g_q_l)[idx] = lv; }
                    else if (s == 1) { ((__nv_bfloat162*)g_k_h)[idx] = hv;
                                       ((__nv_bfloat162*)g_k_l)[idx] = lv; }
                    else             { ((__nv_bfloat162*)g_v_h)[idx] = hv;
                                       ((__nv_bfloat162*)g_v_l)[idx] = lv; }
                } else {
                    *(float2*)&Cout[(size_t)m * N + o] = make_float2(vx, vy);
                }
            }
        }
    }
}

// ---------------------------------------------------------------------------
// Flash attention: bf16x3 mma.sync, FMA fast-exp, 256 q-rows/CTA.
// 64-col KV tiles double-buffered; V natural layout + ldmatrix.trans.
// Each warp owns 32 q-rows (2 row-blocks of 16); K/V fragments reused x2.
// smem: QH 32K | QL 32K | 2 x (KH 8K | KL 8K | VH 8K | VL 8K) = 128KB
// ---------------------------------------------------------------------------
#define FQ_H  0
#define FQ_L  32768
#define FBUF0 65536
#define FBSZ  32768
#define F_KH  0
#define F_KL  8192
#define F_VH  16384
#define F_VL  24576
#define FL_SMEM 131072

__launch_bounds__(256, 1)
__global__ void flash_mma() {
    extern __shared__ char fsm[];
    const uint32_t sb = smem_u32(fsm);
    const int tid = threadIdx.x;
    const int wid = tid >> 5;
    const int lane = tid & 31;
    const int b = blockIdx.y >> 4;
    const int h = blockIdx.y & 15;
    const int i0 = blockIdx.x * 256;

    const int a_row = (lane & 7) + ((lane >> 3) & 1) * 8;
    const int a_kc  = lane >> 4;
    const int b_row = ((lane >> 4) * 8) + (lane & 7);
    const int b_kc  = (lane >> 3) & 1;
    // trans-B lane geometry for natural V: rows = k(t), col-halves by lane>>4
    const int v_row = (lane & 7) + ((lane >> 3) & 1) * 8;
    const int v_dc  = (lane >> 4) * 8;

    const size_t qoff = (size_t)(b * HH + h) * TT * DH;
    const __nv_bfloat16* Qh = g_q_h + qoff + (size_t)i0 * DH;
    const __nv_bfloat16* Ql = g_q_l + qoff + (size_t)i0 * DH;
    const __nv_bfloat16* Kh = g_k_h + qoff;
    const __nv_bfloat16* Kl = g_k_l + qoff;
    const __nv_bfloat16* Vh = g_v_h + qoff;
    const __nv_bfloat16* Vl = g_v_l + qoff;
    const float* dec = g_decay + h * TT;

    // prologue: Q (group 0), tile0 -> buf0 (group 1)
    gload_q256(Qh, sb + FQ_H, tid);
    gload_q256(Ql, sb + FQ_L, tid);
    CP_COMMIT();
    {
        const uint32_t d0 = sb + FBUF0;
        gload_kv64(Kh, d0 + F_KH, tid);
        gload_kv64(Kl, d0 + F_KL, tid);
        gload_kv64(Vh, d0 + F_VH, tid);
        gload_kv64(Vl, d0 + F_VL, tid);
        CP_COMMIT();
    }
    CP_WAIT1();               // Q landed
    __syncthreads();

    uint32_t qh[2][4][4];     // Q-hi persistent per row-block; Q-lo reloaded per tile
#pragma unroll
    for (int blk = 0; blk < 2; blk++)
#pragma unroll
        for (int kt = 0; kt < 4; kt++) {
            uint32_t off = swz((wid * 32 + blk * 16 + a_row) * 128 + (kt * 2 + a_kc) * 16);
            ldmx4(qh[blk][kt], sb + FQ_H + off);
        }

    float O[2][8][4];
#pragma unroll
    for (int blk = 0; blk < 2; blk++)
#pragma unroll
        for (int j = 0; j < 8; j++)
#pragma unroll
            for (int q = 0; q < 4; q++) O[blk][j][q] = 0.f;
    float lsum[2][2] = {{0.f, 0.f}, {0.f, 0.f}};
    const float K1 = 0.125f * 1.44269504f;    // scale * log2(e)

    for (int c = 0; c < 32; c++) {            // 64-wide KV tiles
        CP_WAIT0();
        __syncthreads();

        if (c < 31) {
            const uint32_t dn = sb + FBUF0 + ((c + 1) & 1) * FBSZ;
            const size_t j1 = (size_t)(c + 1) * 64;
            gload_kv64(Kh + j1 * DH, dn + F_KH, tid);
            gload_kv64(Kl + j1 * DH, dn + F_KL, tid);
            gload_kv64(Vh + j1 * DH, dn + F_VH, tid);
            gload_kv64(Vl + j1 * DH, dn + F_VL, tid);
            CP_COMMIT();
        }

        const uint32_t cur = sb + FBUF0 + (c & 1) * FBSZ;
        const uint32_t sKh = cur + F_KH, sKl = cur + F_KL;
        const uint32_t sVh = cur + F_VH, sVl = cur + F_VL;
        const int j0 = c * 64;

        // S = Q K^T (bf16x3), 2 x 16x64
        float s[2][8][4];
#pragma unroll
        for (int blk = 0; blk < 2; blk++)
#pragma unroll
            for (int j = 0; j < 8; j++)
#pragma unroll
                for (int q = 0; q < 4; q++) s[blk][j][q] = 0.f;
#pragma unroll
        for (int kt = 0; kt < 4; kt++) {
            uint32_t qlt[2][4];
#pragma unroll
            for (int blk = 0; blk < 2; blk++)
                ldmx4(qlt[blk], sb + FQ_L +
                      swz((wid * 32 + blk * 16 + a_row) * 128 + (kt * 2 + a_kc) * 16));
#pragma unroll
            for (int ng = 0; ng < 4; ng++) {
                uint32_t kb[4], kc[4];
                uint32_t off = swz((ng * 16 + b_row) * 128 + (kt * 2 + b_kc) * 16);
                ldmx4(kb, sKh + off);
                ldmx4(kc, sKl + off);
#pragma unroll
                for (int blk = 0; blk < 2; blk++) {
                    mma_bf16(s[blk][2 * ng],     qh[blk][kt], kb[0], kb[1]);
                    mma_bf16(s[blk][2 * ng],     qlt[blk],    kb[0], kb[1]);
                    mma_bf16(s[blk][2 * ng],     qh[blk][kt], kc[0], kc[1]);
                    mma_bf16(s[blk][2 * ng + 1], qh[blk][kt], kb[2], kb[3]);
                    mma_bf16(s[blk][2 * ng + 1], qlt[blk],    kb[2], kb[3]);
                    mma_bf16(s[blk][2 * ng + 1], qh[blk][kt], kc[2], kc[3]);
                }
            }
        }

        // p = exp2(s * scale*log2e * decay)
#pragma unroll
        for (int blk = 0; blk < 2; blk++) {
            const int r_lo = i0 + wid * 32 + blk * 16 + (lane >> 2);
#pragma unroll
            for (int j = 0; j < 8; j++) {
                int cbase = j0 + j * 8 + (lane & 3) * 2;
#pragma unroll
                for (int cc = 0; cc < 4; cc++) {
                    int rg = r_lo + ((cc >= 2) ? 8 : 0);
                    int cg = cbase + (cc & 1);
                    float dcy = __ldg(&dec[abs(rg - cg)]);
                    float p = fexp2(s[blk][j][cc] * dcy * K1);
                    s[blk][j][cc] = p;
                    lsum[blk][cc >> 1] += p;
                }
            }
        }

        // O += P V (bf16x3; P from registers; V via ldmatrix.trans on natural layout)
#pragma unroll
        for (int kt = 0; kt < 4; kt++) {
            uint32_t ph[2][4], pl[2][4];
#pragma unroll
            for (int blk = 0; blk < 2; blk++) {
                ph[blk][0] = pack_hl(s[blk][2 * kt][0],     s[blk][2 * kt][1],     pl[blk][0]);
                ph[blk][1] = pack_hl(s[blk][2 * kt][2],     s[blk][2 * kt][3],     pl[blk][1]);
                ph[blk][2] = pack_hl(s[blk][2 * kt + 1][0], s[blk][2 * kt + 1][1], pl[blk][2]);
                ph[blk][3] = pack_hl(s[blk][2 * kt + 1][2], s[blk][2 * kt + 1][3], pl[blk][3]);
            }
#pragma unroll
            for (int ng = 0; ng < 4; ng++) {
                uint32_t vh2[4], vl2[4];
                uint32_t off = swz((kt * 16 + v_row) * 128 + (ng * 16 + v_dc) * 2);
                ldmx4t(vh2, sVh + off);
                ldmx4t(vl2, sVl + off);
#pragma unroll
                for (int blk = 0; blk < 2; blk++) {
                    mma_bf16(O[blk][2 * ng],     ph[blk], vh2[0], vh2[1]);
                    mma_bf16(O[blk][2 * ng],     pl[blk], vh2[0], vh2[1]);
                    mma_bf16(O[blk][2 * ng],     ph[blk], vl2[0], vl2[1]);
                    mma_bf16(O[blk][2 * ng + 1], ph[blk], vh2[2], vh2[3]);
                    mma_bf16(O[blk][2 * ng + 1], pl[blk], vh2[2], vh2[3]);
                    mma_bf16(O[blk][2 * ng + 1], ph[blk], vl2[2], vl2[3]);
                }
            }
        }
    }

#pragma unroll
    for (int blk = 0; blk < 2; blk++) {
        float l0 = lsum[blk][0], l1 = lsum[blk][1];
        l0 += __shfl_xor_sync(0xffffffffu, l0, 1);
        l0 += __shfl_xor_sync(0xffffffffu, l0, 2);
        l1 += __shfl_xor_sync(0xffffffffu, l1, 1);
        l1 += __shfl_xor_sync(0xffffffffu, l1, 2);
        const float inv0 = 1.f / l0;
        const float inv1 = 1.f / l1;
        const int r_lo = i0 + wid * 32 + blk * 16 + (lane >> 2);
#pragma unroll
        for (int j = 0; j < 8; j++) {
            int d = j * 8 + (lane & 3) * 2;
            size_t base0 = ((size_t)b * TT + (size_t)r_lo) * CC + h * DH + d;
            size_t base1 = base0 + 8 * CC;
            uint32_t lo;
            uint32_t hi = pack_hl(O[blk][j][0] * inv0, O[blk][j][1] * inv0, lo);
            ((uint32_t*)g_ao_h)[base0 >> 1] = hi;
            ((uint32_t*)g_ao_l)[base0 >> 1] = lo;
            hi = pack_hl(O[blk][j][2] * inv1, O[blk][j][3] * inv1, lo);
            ((uint32_t*)g_ao_h)[base1 >> 1] = hi;
            ((uint32_t*)g_ao_l)[base1 >> 1] = lo;
        }
    }
}

// ---------------------------------------------------------------------------
extern "C" void kernel_launch(void* const* d_in, const int* in_sizes, int n_in,
                              void* d_out, int out_size) {
    const float* x = (const float*)d_in[0];
    const float* qkv_w = (const float*)d_in[1];
    const float* qkv_b = (const float*)d_in[2];
    const float* proj_w = (const float*)d_in[3];
    const float* proj_b = (const float*)d_in[4];
    const float* lambda_raw = (const float*)d_in[5];
    float* out = (float*)d_out;

    void *p_xh, *p_xl, *p_w1h, *p_w1l, *p_w2h, *p_w2l, *p_aoh, *p_aol;
    cudaGetSymbolAddress(&p_xh, g_x_h);   cudaGetSymbolAddress(&p_xl, g_x_l);
    cudaGetSymbolAddress(&p_w1h, g_w1_h); cudaGetSymbolAddress(&p_w1l, g_w1_l);
    cudaGetSymbolAddress(&p_w2h, g_w2_h); cudaGetSymbolAddress(&p_w2l, g_w2_l);
    cudaGetSymbolAddress(&p_aoh, g_ao_h); cudaGetSymbolAddress(&p_aol, g_ao_l);

    cudaFuncSetAttribute(flash_mma, cudaFuncAttributeMaxDynamicSharedMemorySize, FL_SMEM);
    cudaFuncSetAttribute(gemm_mma<0>, cudaFuncAttributeMaxDynamicSharedMemorySize, GEMM_SMEM);
    cudaFuncSetAttribute(gemm_mma<1>, cudaFuncAttributeMaxDynamicSharedMemorySize, GEMM_SMEM);

    decay_kernel<<<(HH * TT + 255) / 256, 256>>>(lambda_raw);

    split_bf16<<<4194304 / 4 / 256, 256>>>(x, (__nv_bfloat16*)p_xh, (__nv_bfloat16*)p_xl,
                                           4194304 / 4);
    split_bf16<<<3145728 / 4 / 256, 256>>>(qkv_w, (__nv_bfloat16*)p_w1h, (__nv_bfloat16*)p_w1l,
                                           3145728 / 4);
    split_bf16<<<1048576 / 4 / 256, 256>>>(proj_w, (__nv_bfloat16*)p_w2h, (__nv_bfloat16*)p_w2l,
                                           1048576 / 4);

    gemm_mma<0><<<dim3(3072 / 128, 4096 / 256), 256, GEMM_SMEM>>>(
        (const __nv_bfloat16*)p_xh, (const __nv_bfloat16*)p_xl,
        (const __nv_bfloat16*)p_w1h, (const __nv_bfloat16*)p_w1l, qkv_b, nullptr, 3072);

    flash_mma<<<dim3(TT / 256, BB * HH), 256, FL_SMEM>>>();

    gemm_mma<1><<<dim3(1024 / 128, 4096 / 256), 256, GEMM_SMEM>>>(
        (const __nv_bfloat16*)p_aoh, (const __nv_bfloat16*)p_aol,
        (const __nv_bfloat16*)p_w2h, (const __nv_bfloat16*)p_w2l, proj_b, out, 1024);
}

// round 10
// speedup vs baseline: 1.3298x; 1.3298x over previous
#include <cuda_runtime.h>
#include <cuda_fp16.h>
#include <math.h>
#include <stdint.h>

#define BB 2
#define TT 2048
#define CC 1024
#define HH 16
#define DH 64

// ---------------------------------------------------------------------------
// Scratch (device globals: allocation-free rule). fp16 planes.
// A-side tensors keep hi+lo; B-side tensors hi only.
// ---------------------------------------------------------------------------
__device__ float g_decay[HH * TT];                 // [h][dist]

__device__ __half g_q_h[4194304], g_q_l[4194304];  // [b][h][t][d]
__device__ __half g_k_h[4194304];                  // [b][h][t][d]
__device__ __half g_v_h[4194304];                  // [b][h][t][d]
__device__ __half g_ao_h[4194304], g_ao_l[4194304];

__device__ __half g_x_h[4194304],  g_x_l[4194304];
__device__ __half g_w1_h[3145728];
__device__ __half g_w2_h[1048576];

// ---------------------------------------------------------------------------
// helpers
// ---------------------------------------------------------------------------
__device__ __forceinline__ uint32_t smem_u32(const void* p) {
    uint32_t a;
    asm("{ .reg .u64 t; cvta.to.shared.u64 t, %1; cvt.u32.u64 %0, t; }" : "=r"(a) : "l"(p));
    return a;
}
__device__ __forceinline__ uint32_t swz(uint32_t off) {     // 128B rows
    return off ^ ((off >> 3) & 0x70);
}
__device__ __forceinline__ void ldmx4(uint32_t* r, uint32_t addr) {
    asm volatile("ldmatrix.sync.aligned.m8n8.x4.shared.b16 {%0,%1,%2,%3}, [%4];"
                 : "=r"(r[0]), "=r"(r[1]), "=r"(r[2]), "=r"(r[3]) : "r"(addr));
}
__device__ __forceinline__ void ldmx4t(uint32_t* r, uint32_t addr) {
    asm volatile("ldmatrix.sync.aligned.m8n8.x4.trans.shared.b16 {%0,%1,%2,%3}, [%4];"
                 : "=r"(r[0]), "=r"(r[1]), "=r"(r[2]), "=r"(r[3]) : "r"(addr));
}
__device__ __forceinline__ void mma_f16(float* c, const uint32_t* a, uint32_t b0, uint32_t b1) {
    asm volatile("mma.sync.aligned.m16n8k16.row.col.f32.f16.f16.f32 "
                 "{%0,%1,%2,%3}, {%4,%5,%6,%7}, {%8,%9}, {%0,%1,%2,%3};"
                 : "+f"(c[0]), "+f"(c[1]), "+f"(c[2]), "+f"(c[3])
                 : "r"(a[0]), "r"(a[1]), "r"(a[2]), "r"(a[3]), "r"(b0), "r"(b1));
}
__device__ __forceinline__ void cpa16(uint32_t dst, const void* src) {
    asm volatile("cp.async.cg.shared.global [%0], [%1], 16;" :: "r"(dst), "l"(src));
}
#define CP_COMMIT() asm volatile("cp.async.commit_group;" ::: "memory")
#define CP_WAIT1()  asm volatile("cp.async.wait_group 1;" ::: "memory")
#define CP_WAIT0()  asm volatile("cp.async.wait_group 0;" ::: "memory")

// fast 2^y via FMA only (no MUFU)
__device__ __forceinline__ float fexp2(float y) {
    y = fminf(fmaxf(y, -120.f), 80.f);
    float z = y + 12582912.f;
    int iz = __float_as_int(z);
    float f = y - (z - 12582912.f);
    float p = 1.3333558e-3f;
    p = fmaf(p, f, 9.6181291e-3f);
    p = fmaf(p, f, 5.5504109e-2f);
    p = fmaf(p, f, 2.4022651e-1f);
    p = fmaf(p, f, 6.9314718e-1f);
    p = fmaf(p, f, 1.0f);
    return p * __int_as_float((iz + (127 - 0x4B400000)) << 23);
}
// split pair -> packed f16x2 hi (ret) and lo (out param)
__device__ __forceinline__ uint32_t pack_hl16(float x, float y, uint32_t& lo) {
    __half hx = __float2half_rn(x), hy = __float2half_rn(y);
    __half lx = __float2half_rn(x - __half2float(hx));
    __half ly = __float2half_rn(y - __half2float(hy));
    lo = ((uint32_t)__half_as_ushort(ly) << 16) | (uint32_t)__half_as_ushort(lx);
    return ((uint32_t)__half_as_ushort(hy) << 16) | (uint32_t)__half_as_ushort(hx);
}

// ---------------------------------------------------------------------------
// fp16 conversion kernels
// ---------------------------------------------------------------------------
__global__ void split_fp16(const float* __restrict__ src, __half* __restrict__ hi,
                           __half* __restrict__ lo, int n4) {
    int i = blockIdx.x * blockDim.x + threadIdx.x;
    if (i < n4) {
        float4 v = ((const float4*)src)[i];
        __half h0 = __float2half_rn(v.x), h1 = __float2half_rn(v.y);
        __half h2 = __float2half_rn(v.z), h3 = __float2half_rn(v.w);
        __half2* H = (__half2*)hi;
        __half2* L = (__half2*)lo;
        H[i * 2]     = __half2(h0, h1);
        H[i * 2 + 1] = __half2(h2, h3);
        L[i * 2]     = __half2(__float2half_rn(v.x - __half2float(h0)),
                               __float2half_rn(v.y - __half2float(h1)));
        L[i * 2 + 1] = __half2(__float2half_rn(v.z - __half2float(h2)),
                               __float2half_rn(v.w - __half2float(h3)));
    }
}
__global__ void conv_fp16(const float* __restrict__ src, __half* __restrict__ hi, int n4) {
    int i = blockIdx.x * blockDim.x + threadIdx.x;
    if (i < n4) {
        float4 v = ((const float4*)src)[i];
        __half2* H = (__half2*)hi;
        H[i * 2]     = __half2(__float2half_rn(v.x), __float2half_rn(v.y));
        H[i * 2 + 1] = __half2(__float2half_rn(v.z), __float2half_rn(v.w));
    }
}

__global__ void decay_kernel(const float* __restrict__ lambda_raw) {
    int idx = blockIdx.x * blockDim.x + threadIdx.x;
    if (idx < HH * TT) {
        int h = idx / TT;
        int d = idx % TT;
        float lam = log1pf(expf(lambda_raw[h]));
        g_decay[idx] = expf(-lam * (float)d);
    }
}

// ---------------------------------------------------------------------------
// async tile loaders (fp16: 64 elems = 128B per row, same geometry as before)
// ---------------------------------------------------------------------------
__device__ __forceinline__ void gload_a256(const __half* __restrict__ g,
                                           uint32_t dst, int tid) {
#pragma unroll
    for (int i = 0; i < 8; i++) {
        int slot = tid + i * 256;
        int row = slot >> 3;
        int c16 = slot & 7;
        cpa16(dst + swz(row * 128 + c16 * 16), g + (size_t)row * 1024 + c16 * 8);
    }
}
__device__ __forceinline__ void gload_b128(const __half* __restrict__ g,
                                           uint32_t dst, int tid) {
#pragma unroll
    for (int i = 0; i < 4; i++) {
        int slot = tid + i * 256;
        int row = slot >> 3;
        int c16 = slot & 7;
        cpa16(dst + swz(row * 128 + c16 * 16), g + (size_t)row * 1024 + c16 * 8);
    }
}
__device__ __forceinline__ void gload_q256(const __half* __restrict__ g,
                                           uint32_t dst, int tid) {
#pragma unroll
    for (int i = 0; i < 8; i++) {
        int slot = tid + i * 256;
        int row = slot >> 3;
        int c16 = slot & 7;
        cpa16(dst + swz(row * 128 + c16 * 16), g + (size_t)row * 64 + c16 * 8);
    }
}
__device__ __forceinline__ void gload_kv64(const __half* __restrict__ g,
                                           uint32_t dst, int tid) {
#pragma unroll
    for (int i = 0; i < 2; i++) {
        int slot = tid + i * 256;
        int row = slot >> 3;
        int c16 = slot & 7;
        cpa16(dst + swz(row * 128 + c16 * 16), g + (size_t)row * 64 + c16 * 8);
    }
}

// ---------------------------------------------------------------------------
// fp16x2 mma.sync NT GEMM: C = A * Bh^T + bias,  A = Ah + Al (fp16 pair).
// 256x128 CTA tile, BK=64, double-buffered.
// smem buf: AH 32K | AL 32K | BH 16K = 80KB; x2 = 160KB
// ---------------------------------------------------------------------------
#define GA_H 0
#define GA_L 32768
#define GB_H 65536
#define GBUF 81920
#define GEMM_SMEM 163840

template <int EPI>
__launch_bounds__(256, 1)
__global__ void gemm_mma(const __half* __restrict__ Ah, const __half* __restrict__ Al,
                         const __half* __restrict__ Bh,
                         const float* __restrict__ bias, float* __restrict__ Cout, int N) {
    extern __shared__ char smem[];
    const uint32_t sb = smem_u32(smem);
    const int tid = threadIdx.x;
    const int wid = tid >> 5;
    const int lane = tid & 31;
    const int wm = wid & 3;
    const int wn = wid >> 2;
    const int n0 = blockIdx.x * 128;
    const int m0 = blockIdx.y * 256;

    const int a_row = (lane & 7) + ((lane >> 3) & 1) * 8;
    const int a_kc  = lane >> 4;
    const int b_row = ((lane >> 4) * 8) + (lane & 7);
    const int b_kc  = (lane >> 3) & 1;

    const __half* Abase_h = Ah + (size_t)m0 * 1024;
    const __half* Abase_l = Al + (size_t)m0 * 1024;
    const __half* Bbase_h = Bh + (size_t)n0 * 1024;

    float acc[4][8][4];
#pragma unroll
    for (int i = 0; i < 4; i++)
#pragma unroll
        for (int j = 0; j < 8; j++)
#pragma unroll
            for (int q = 0; q < 4; q++) acc[i][j][q] = 0.f;

    gload_a256(Abase_h, sb + GA_H, tid);
    gload_a256(Abase_l, sb + GA_L, tid);
    gload_b128(Bbase_h, sb + GB_H, tid);
    CP_COMMIT();

    for (int c = 0; c < 16; c++) {
        const uint32_t cur = (c & 1) ? GBUF : 0u;
        const uint32_t nxt = cur ^ GBUF;
        if (c < 15) {
            const size_t ka = (size_t)(c + 1) * 64;
            gload_a256(Abase_h + ka, sb + nxt + GA_H, tid);
            gload_a256(Abase_l + ka, sb + nxt + GA_L, tid);
            gload_b128(Bbase_h + ka, sb + nxt + GB_H, tid);
            CP_COMMIT();
            CP_WAIT1();
        } else {
            CP_WAIT0();
        }
        __syncthreads();

        const uint32_t sAh = sb + cur + GA_H, sAl = sb + cur + GA_L;
        const uint32_t sBh = sb + cur + GB_H;
#pragma unroll
        for (int kt = 0; kt < 4; kt++) {
            uint32_t ah[4][4], al[4][4];
#pragma unroll
            for (int mi = 0; mi < 4; mi++) {
                uint32_t off = swz((wm * 64 + mi * 16 + a_row) * 128 + (kt * 2 + a_kc) * 16);
                ldmx4(ah[mi], sAh + off);
                ldmx4(al[mi], sAl + off);
            }
#pragma unroll
            for (int ng = 0; ng < 4; ng++) {
                uint32_t bh[4];
                uint32_t off = swz((wn * 64 + ng * 16 + b_row) * 128 + (kt * 2 + b_kc) * 16);
                ldmx4(bh, sBh + off);
#pragma unroll
                for (int mi = 0; mi < 4; mi++) {
                    mma_f16(acc[mi][2 * ng],     ah[mi], bh[0], bh[1]);
                    mma_f16(acc[mi][2 * ng],     al[mi], bh[0], bh[1]);
                    mma_f16(acc[mi][2 * ng + 1], ah[mi], bh[2], bh[3]);
                    mma_f16(acc[mi][2 * ng + 1], al[mi], bh[2], bh[3]);
                }
            }
        }
        __syncthreads();
    }

#pragma unroll
    for (int mi = 0; mi < 4; mi++) {
#pragma unroll
        for (int j = 0; j < 8; j++) {
            int row = m0 + wm * 64 + mi * 16 + (lane >> 2);
            int o = n0 + wn * 64 + j * 8 + (lane & 3) * 2;
            float b0 = bias[o], b1 = bias[o + 1];
#pragma unroll
            for (int half = 0; half < 2; half++) {
                int m = row + half * 8;
                float vx = acc[mi][j][half * 2] + b0;
                float vy = acc[mi][j][half * 2 + 1] + b1;
                if (EPI == 0) {
                    int s = o >> 10;
                    int rem = o & 1023;
                    int hh = rem >> 6;
                    int d = rem & 63;
                    int bb = m >> 11;
                    int t = m & 2047;
                    size_t idx = (((size_t)(bb * HH + hh) * TT + t) * DH + d) >> 1;
                    __half h0 = __float2half_rn(vx);
                    __half h1 = __float2half_rn(vy);
                    __half2 hv(h0, h1);
                    if (s == 0) {        // Q: hi + lo
                        __half2 lv(__float2half_rn(vx - __half2float(h0)),
                                   __float2half_rn(vy - __half2float(h1)));
                        ((__half2*)g_q_h)[idx] = hv;
                        ((__half2*)g_q_l)[idx] = lv;
                    } else if (s == 1) { // K: hi only
                        ((__half2*)g_k_h)[idx] = hv;
                    } else {             // V: hi only
                        ((__half2*)g_v_h)[idx] = hv;
                    }
                } else {
                    *(float2*)&Cout[(size_t)m * N + o] = make_float2(vx, vy);
                }
            }
        }
    }
}

// ---------------------------------------------------------------------------
// Flash attention: fp16x2 mma.sync, FMA fast-exp, 256 q-rows/CTA.
// 64-col KV tiles double-buffered; V natural layout + ldmatrix.trans.
// smem: QH 32K | QL 32K | 2 x (KH 8K | VH 8K) = 96KB
// ---------------------------------------------------------------------------
#define FQ_H  0
#define FQ_L  32768
#define FBUF0 65536
#define FBSZ  16384
#define F_KH  0
#define F_VH  8192
#define FL_SMEM 98304

__launch_bounds__(256, 1)
__global__ void flash_mma() {
    extern __shared__ char fsm[];
    const uint32_t sb = smem_u32(fsm);
    const int tid = threadIdx.x;
    const int wid = tid >> 5;
    const int lane = tid & 31;
    const int b = blockIdx.y >> 4;
    const int h = blockIdx.y & 15;
    const int i0 = blockIdx.x * 256;

    const int a_row = (lane & 7) + ((lane >> 3) & 1) * 8;
    const int a_kc  = lane >> 4;
    const int b_row = ((lane >> 4) * 8) + (lane & 7);
    const int b_kc  = (lane >> 3) & 1;
    const int v_row = (lane & 7) + ((lane >> 3) & 1) * 8;
    const int v_dc  = (lane >> 4) * 8;

    const size_t qoff = (size_t)(b * HH + h) * TT * DH;
    const __half* Qh = g_q_h + qoff + (size_t)i0 * DH;
    const __half* Ql = g_q_l + qoff + (size_t)i0 * DH;
    const __half* Kh = g_k_h + qoff;
    const __half* Vh = g_v_h + qoff;
    const float* dec = g_decay + h * TT;

    gload_q256(Qh, sb + FQ_H, tid);
    gload_q256(Ql, sb + FQ_L, tid);
    CP_COMMIT();
    {
        const uint32_t d0 = sb + FBUF0;
        gload_kv64(Kh, d0 + F_KH, tid);
        gload_kv64(Vh, d0 + F_VH, tid);
        CP_COMMIT();
    }
    CP_WAIT1();               // Q landed
    __syncthreads();

    uint32_t qh[2][4][4];     // Q-hi persistent; Q-lo reloaded per tile
#pragma unroll
    for (int blk = 0; blk < 2; blk++)
#pragma unroll
        for (int kt = 0; kt < 4; kt++) {
            uint32_t off = swz((wid * 32 + blk * 16 + a_row) * 128 + (kt * 2 + a_kc) * 16);
            ldmx4(qh[blk][kt], sb + FQ_H + off);
        }

    float O[2][8][4];
#pragma unroll
    for (int blk = 0; blk < 2; blk++)
#pragma unroll
        for (int j = 0; j < 8; j++)
#pragma unroll
            for (int q = 0; q < 4; q++) O[blk][j][q] = 0.f;
    float lsum[2][2] = {{0.f, 0.f}, {0.f, 0.f}};
    const float K1 = 0.125f * 1.44269504f;    // scale * log2(e)

    for (int c = 0; c < 32; c++) {            // 64-wide KV tiles
        CP_WAIT0();
        __syncthreads();

        if (c < 31) {
            const uint32_t dn = sb + FBUF0 + ((c + 1) & 1) * FBSZ;
            const size_t j1 = (size_t)(c + 1) * 64;
            gload_kv64(Kh + j1 * DH, dn + F_KH, tid);
            gload_kv64(Vh + j1 * DH, dn + F_VH, tid);
            CP_COMMIT();
        }

        const uint32_t cur = sb + FBUF0 + (c & 1) * FBSZ;
        const uint32_t sKh = cur + F_KH;
        const uint32_t sVh = cur + F_VH;
        const int j0 = c * 64;

        // S = Q Kh^T (fp16x2 on Q)
        float s[2][8][4];
#pragma unroll
        for (int blk = 0; blk < 2; blk++)
#pragma unroll
            for (int j = 0; j < 8; j++)
#pragma unroll
                for (int q = 0; q < 4; q++) s[blk][j][q] = 0.f;
#pragma unroll
        for (int kt = 0; kt < 4; kt++) {
            uint32_t qlt[2][4];
#pragma unroll
            for (int blk = 0; blk < 2; blk++)
                ldmx4(qlt[blk], sb + FQ_L +
                      swz((wid * 32 + blk * 16 + a_row) * 128 + (kt * 2 + a_kc) * 16));
#pragma unroll
            for (int ng = 0; ng < 4; ng++) {
                uint32_t kb[4];
                uint32_t off = swz((ng * 16 + b_row) * 128 + (kt * 2 + b_kc) * 16);
                ldmx4(kb, sKh + off);
#pragma unroll
                for (int blk = 0; blk < 2; blk++) {
                    mma_f16(s[blk][2 * ng],     qh[blk][kt], kb[0], kb[1]);
                    mma_f16(s[blk][2 * ng],     qlt[blk],    kb[0], kb[1]);
                    mma_f16(s[blk][2 * ng + 1], qh[blk][kt], kb[2], kb[3]);
                    mma_f16(s[blk][2 * ng + 1], qlt[blk],    kb[2], kb[3]);
                }
            }
        }

        // p = exp2(s * scale*log2e * decay)
#pragma unroll
        for (int blk = 0; blk < 2; blk++) {
            const int r_lo = i0 + wid * 32 + blk * 16 + (lane >> 2);
#pragma unroll
            for (int j = 0; j < 8; j++) {
                int cbase = j0 + j * 8 + (lane & 3) * 2;
#pragma unroll
                for (int cc = 0; cc < 4; cc++) {
                    int rg = r_lo + ((cc >= 2) ? 8 : 0);
                    int cg = cbase + (cc & 1);
                    float dcy = __ldg(&dec[abs(rg - cg)]);
                    float p = fexp2(s[blk][j][cc] * dcy * K1);
                    s[blk][j][cc] = p;
                    lsum[blk][cc >> 1] += p;
                }
            }
        }

        // O += P Vh (fp16x2 on P; V via ldmatrix.trans)
#pragma unroll
        for (int kt = 0; kt < 4; kt++) {
            uint32_t ph[2][4], pl[2][4];
#pragma unroll
            for (int blk = 0; blk < 2; blk++) {
                ph[blk][0] = pack_hl16(s[blk][2 * kt][0],     s[blk][2 * kt][1],     pl[blk][0]);
                ph[blk][1] = pack_hl16(s[blk][2 * kt][2],     s[blk][2 * kt][3],     pl[blk][1]);
                ph[blk][2] = pack_hl16(s[blk][2 * kt + 1][0], s[blk][2 * kt + 1][1], pl[blk][2]);
                ph[blk][3] = pack_hl16(s[blk][2 * kt + 1][2], s[blk][2 * kt + 1][3], pl[blk][3]);
            }
#pragma unroll
            for (int ng = 0; ng < 4; ng++) {
                uint32_t vh2[4];
                uint32_t off = swz((kt * 16 + v_row) * 128 + (ng * 16 + v_dc) * 2);
                ldmx4t(vh2, sVh + off);
#pragma unroll
                for (int blk = 0; blk < 2; blk++) {
                    mma_f16(O[blk][2 * ng],     ph[blk], vh2[0], vh2[1]);
                    mma_f16(O[blk][2 * ng],     pl[blk], vh2[0], vh2[1]);
                    mma_f16(O[blk][2 * ng + 1], ph[blk], vh2[2], vh2[3]);
                    mma_f16(O[blk][2 * ng + 1], pl[blk], vh2[2], vh2[3]);
                }
            }
        }
    }

#pragma unroll
    for (int blk = 0; blk < 2; blk++) {
        float l0 = lsum[blk][0], l1 = lsum[blk][1];
        l0 += __shfl_xor_sync(0xffffffffu, l0, 1);
        l0 += __shfl_xor_sync(0xffffffffu, l0, 2);
        l1 += __shfl_xor_sync(0xffffffffu, l1, 1);
        l1 += __shfl_xor_sync(0xffffffffu, l1, 2);
        const float inv0 = 1.f / l0;
        const float inv1 = 1.f / l1;
        const int r_lo = i0 + wid * 32 + blk * 16 + (lane >> 2);
#pragma unroll
        for (int j = 0; j < 8; j++) {
            int d = j * 8 + (lane & 3) * 2;
            size_t base0 = ((size_t)b * TT + (size_t)r_lo) * CC + h * DH + d;
            size_t base1 = base0 + 8 * CC;
            uint32_t lo;
            uint32_t hi = pack_hl16(O[blk][j][0] * inv0, O[blk][j][1] * inv0, lo);
            ((uint32_t*)g_ao_h)[base0 >> 1] = hi;
            ((uint32_t*)g_ao_l)[base0 >> 1] = lo;
            hi = pack_hl16(O[blk][j][2] * inv1, O[blk][j][3] * inv1, lo);
            ((uint32_t*)g_ao_h)[base1 >> 1] = hi;
            ((uint32_t*)g_ao_l)[base1 >> 1] = lo;
        }
    }
}

// ---------------------------------------------------------------------------
extern "C" void kernel_launch(void* const* d_in, const int* in_sizes, int n_in,
                              void* d_out, int out_size) {
    const float* x = (const float*)d_in[0];
    const float* qkv_w = (const float*)d_in[1];
    const float* qkv_b = (const float*)d_in[2];
    const float* proj_w = (const float*)d_in[3];
    const float* proj_b = (const float*)d_in[4];
    const float* lambda_raw = (const float*)d_in[5];
    float* out = (float*)d_out;

    void *p_xh, *p_xl, *p_w1h, *p_w2h, *p_aoh, *p_aol;
    cudaGetSymbolAddress(&p_xh, g_x_h);   cudaGetSymbolAddress(&p_xl, g_x_l);
    cudaGetSymbolAddress(&p_w1h, g_w1_h);
    cudaGetSymbolAddress(&p_w2h, g_w2_h);
    cudaGetSymbolAddress(&p_aoh, g_ao_h); cudaGetSymbolAddress(&p_aol, g_ao_l);

    cudaFuncSetAttribute(flash_mma, cudaFuncAttributeMaxDynamicSharedMemorySize, FL_SMEM);
    cudaFuncSetAttribute(gemm_mma<0>, cudaFuncAttributeMaxDynamicSharedMemorySize, GEMM_SMEM);
    cudaFuncSetAttribute(gemm_mma<1>, cudaFuncAttributeMaxDynamicSharedMemorySize, GEMM_SMEM);

    decay_kernel<<<(HH * TT + 255) / 256, 256>>>(lambda_raw);

    split_fp16<<<4194304 / 4 / 256, 256>>>(x, (__half*)p_xh, (__half*)p_xl, 4194304 / 4);
    conv_fp16<<<3145728 / 4 / 256, 256>>>(qkv_w, (__half*)p_w1h, 3145728 / 4);
    conv_fp16<<<1048576 / 4 / 256, 256>>>(proj_w, (__half*)p_w2h, 1048576 / 4);

    gemm_mma<0><<<dim3(3072 / 128, 4096 / 256), 256, GEMM_SMEM>>>(
        (const __half*)p_xh, (const __half*)p_xl, (const __half*)p_w1h,
        qkv_b, nullptr, 3072);

    flash_mma<<<dim3(TT / 256, BB * HH), 256, FL_SMEM>>>();

    gemm_mma<1><<<dim3(1024 / 128, 4096 / 256), 256, GEMM_SMEM>>>(
        (const __half*)p_aoh, (const __half*)p_aol, (const __half*)p_w2h,
        proj_b, out, 1024);
}

// round 11
// speedup vs baseline: 2.1703x; 1.6320x over previous
#include <cuda_runtime.h>
#include <cuda_fp16.h>
#include <math.h>
#include <stdint.h>

#define BB 2
#define TT 2048
#define CC 1024
#define HH 16
#define DH 64

// ---------------------------------------------------------------------------
// Scratch (device globals: allocation-free rule). Pure fp16 planes.
// ---------------------------------------------------------------------------
__device__ float g_decay[HH * TT];                 // [h][dist]

__device__ __half g_q_h[4194304];                  // [b][h][t][d]
__device__ __half g_k_h[4194304];                  // [b][h][t][d]
__device__ __half g_v_h[4194304];                  // [b][h][t][d]
__device__ __half g_ao_h[4194304];                 // [b*t][c]

__device__ __half g_x_h[4194304];
__device__ __half g_w1_h[3145728];
__device__ __half g_w2_h[1048576];

// ---------------------------------------------------------------------------
// helpers
// ---------------------------------------------------------------------------
__device__ __forceinline__ uint32_t smem_u32(const void* p) {
    uint32_t a;
    asm("{ .reg .u64 t; cvta.to.shared.u64 t, %1; cvt.u32.u64 %0, t; }" : "=r"(a) : "l"(p));
    return a;
}
__device__ __forceinline__ uint32_t swz(uint32_t off) {     // 128B rows
    return off ^ ((off >> 3) & 0x70);
}
__device__ __forceinline__ void ldmx4(uint32_t* r, uint32_t addr) {
    asm volatile("ldmatrix.sync.aligned.m8n8.x4.shared.b16 {%0,%1,%2,%3}, [%4];"
                 : "=r"(r[0]), "=r"(r[1]), "=r"(r[2]), "=r"(r[3]) : "r"(addr));
}
__device__ __forceinline__ void ldmx4t(uint32_t* r, uint32_t addr) {
    asm volatile("ldmatrix.sync.aligned.m8n8.x4.trans.shared.b16 {%0,%1,%2,%3}, [%4];"
                 : "=r"(r[0]), "=r"(r[1]), "=r"(r[2]), "=r"(r[3]) : "r"(addr));
}
__device__ __forceinline__ void mma_f16(float* c, const uint32_t* a, uint32_t b0, uint32_t b1) {
    asm volatile("mma.sync.aligned.m16n8k16.row.col.f32.f16.f16.f32 "
                 "{%0,%1,%2,%3}, {%4,%5,%6,%7}, {%8,%9}, {%0,%1,%2,%3};"
                 : "+f"(c[0]), "+f"(c[1]), "+f"(c[2]), "+f"(c[3])
                 : "r"(a[0]), "r"(a[1]), "r"(a[2]), "r"(a[3]), "r"(b0), "r"(b1));
}
__device__ __forceinline__ void cpa16(uint32_t dst, const void* src) {
    asm volatile("cp.async.cg.shared.global [%0], [%1], 16;" :: "r"(dst), "l"(src));
}
#define CP_COMMIT() asm volatile("cp.async.commit_group;" ::: "memory")
#define CP_WAIT1()  asm volatile("cp.async.wait_group 1;" ::: "memory")
#define CP_WAIT0()  asm volatile("cp.async.wait_group 0;" ::: "memory")

// fast 2^y via FMA only (no MUFU)
__device__ __forceinline__ float fexp2(float y) {
    y = fminf(fmaxf(y, -120.f), 80.f);
    float z = y + 12582912.f;
    int iz = __float_as_int(z);
    float f = y - (z - 12582912.f);
    float p = 1.3333558e-3f;
    p = fmaf(p, f, 9.6181291e-3f);
    p = fmaf(p, f, 5.5504109e-2f);
    p = fmaf(p, f, 2.4022651e-1f);
    p = fmaf(p, f, 6.9314718e-1f);
    p = fmaf(p, f, 1.0f);
    return p * __int_as_float((iz + (127 - 0x4B400000)) << 23);
}
__device__ __forceinline__ uint32_t pack16(float x, float y) {
    __half hx = __float2half_rn(x), hy = __float2half_rn(y);
    return ((uint32_t)__half_as_ushort(hy) << 16) | (uint32_t)__half_as_ushort(hx);
}

// ---------------------------------------------------------------------------
__global__ void conv_fp16(const float* __restrict__ src, __half* __restrict__ hi, int n4) {
    int i = blockIdx.x * blockDim.x + threadIdx.x;
    if (i < n4) {
        float4 v = ((const float4*)src)[i];
        __half2* H = (__half2*)hi;
        H[i * 2]     = __half2(__float2half_rn(v.x), __float2half_rn(v.y));
        H[i * 2 + 1] = __half2(__float2half_rn(v.z), __float2half_rn(v.w));
    }
}

__global__ void decay_kernel(const float* __restrict__ lambda_raw) {
    int idx = blockIdx.x * blockDim.x + threadIdx.x;
    if (idx < HH * TT) {
        int h = idx / TT;
        int d = idx % TT;
        float lam = log1pf(expf(lambda_raw[h]));
        g_decay[idx] = expf(-lam * (float)d);
    }
}

// ---------------------------------------------------------------------------
// async tile loaders
// ---------------------------------------------------------------------------
__device__ __forceinline__ void gload_a256(const __half* __restrict__ g,
                                           uint32_t dst, int tid) {
#pragma unroll
    for (int i = 0; i < 8; i++) {
        int slot = tid + i * 256;
        int row = slot >> 3;
        int c16 = slot & 7;
        cpa16(dst + swz(row * 128 + c16 * 16), g + (size_t)row * 1024 + c16 * 8);
    }
}
__device__ __forceinline__ void gload_b128(const __half* __restrict__ g,
                                           uint32_t dst, int tid) {
#pragma unroll
    for (int i = 0; i < 4; i++) {
        int slot = tid + i * 256;
        int row = slot >> 3;
        int c16 = slot & 7;
        cpa16(dst + swz(row * 128 + c16 * 16), g + (size_t)row * 1024 + c16 * 8);
    }
}
__device__ __forceinline__ void gload_q256(const __half* __restrict__ g,
                                           uint32_t dst, int tid) {
#pragma unroll
    for (int i = 0; i < 8; i++) {
        int slot = tid + i * 256;
        int row = slot >> 3;
        int c16 = slot & 7;
        cpa16(dst + swz(row * 128 + c16 * 16), g + (size_t)row * 64 + c16 * 8);
    }
}
__device__ __forceinline__ void gload_kv64(const __half* __restrict__ g,
                                           uint32_t dst, int tid) {
#pragma unroll
    for (int i = 0; i < 2; i++) {
        int slot = tid + i * 256;
        int row = slot >> 3;
        int c16 = slot & 7;
        cpa16(dst + swz(row * 128 + c16 * 16), g + (size_t)row * 64 + c16 * 8);
    }
}

// ---------------------------------------------------------------------------
// fp16 mma.sync NT GEMM: C = A * B^T + bias. 256x128 CTA tile, BK=64,
// double-buffered. smem buf: AH 32K | BH 16K = 48KB; x2 = 96KB
// ---------------------------------------------------------------------------
#define GA_H 0
#define GB_H 32768
#define GBUF 49152
#define GEMM_SMEM 98304

template <int EPI>
__launch_bounds__(256, 1)
__global__ void gemm_mma(const __half* __restrict__ Ah, const __half* __restrict__ Bh,
                         const float* __restrict__ bias, float* __restrict__ Cout, int N) {
    extern __shared__ char smem[];
    const uint32_t sb = smem_u32(smem);
    const int tid = threadIdx.x;
    const int wid = tid >> 5;
    const int lane = tid & 31;
    const int wm = wid & 3;
    const int wn = wid >> 2;
    const int n0 = blockIdx.x * 128;
    const int m0 = blockIdx.y * 256;

    const int a_row = (lane & 7) + ((lane >> 3) & 1) * 8;
    const int a_kc  = lane >> 4;
    const int b_row = ((lane >> 4) * 8) + (lane & 7);
    const int b_kc  = (lane >> 3) & 1;

    const __half* Abase = Ah + (size_t)m0 * 1024;
    const __half* Bbase = Bh + (size_t)n0 * 1024;

    float acc[4][8][4];
#pragma unroll
    for (int i = 0; i < 4; i++)
#pragma unroll
        for (int j = 0; j < 8; j++)
#pragma unroll
            for (int q = 0; q < 4; q++) acc[i][j][q] = 0.f;

    gload_a256(Abase, sb + GA_H, tid);
    gload_b128(Bbase, sb + GB_H, tid);
    CP_COMMIT();

    for (int c = 0; c < 16; c++) {
        const uint32_t cur = (c & 1) ? GBUF : 0u;
        const uint32_t nxt = cur ^ GBUF;
        if (c < 15) {
            const size_t ka = (size_t)(c + 1) * 64;
            gload_a256(Abase + ka, sb + nxt + GA_H, tid);
            gload_b128(Bbase + ka, sb + nxt + GB_H, tid);
            CP_COMMIT();
            CP_WAIT1();
        } else {
            CP_WAIT0();
        }
        __syncthreads();

        const uint32_t sAh = sb + cur + GA_H;
        const uint32_t sBh = sb + cur + GB_H;
#pragma unroll
        for (int kt = 0; kt < 4; kt++) {
            uint32_t ah[4][4];
#pragma unroll
            for (int mi = 0; mi < 4; mi++) {
                uint32_t off = swz((wm * 64 + mi * 16 + a_row) * 128 + (kt * 2 + a_kc) * 16);
                ldmx4(ah[mi], sAh + off);
            }
#pragma unroll
            for (int ng = 0; ng < 4; ng++) {
                uint32_t bh[4];
                uint32_t off = swz((wn * 64 + ng * 16 + b_row) * 128 + (kt * 2 + b_kc) * 16);
                ldmx4(bh, sBh + off);
#pragma unroll
                for (int mi = 0; mi < 4; mi++) {
                    mma_f16(acc[mi][2 * ng],     ah[mi], bh[0], bh[1]);
                    mma_f16(acc[mi][2 * ng + 1], ah[mi], bh[2], bh[3]);
                }
            }
        }
        __syncthreads();
    }

#pragma unroll
    for (int mi = 0; mi < 4; mi++) {
#pragma unroll
        for (int j = 0; j < 8; j++) {
            int row = m0 + wm * 64 + mi * 16 + (lane >> 2);
            int o = n0 + wn * 64 + j * 8 + (lane & 3) * 2;
            float b0 = bias[o], b1 = bias[o + 1];
#pragma unroll
            for (int half = 0; half < 2; half++) {
                int m = row + half * 8;
                float vx = acc[mi][j][half * 2] + b0;
                float vy = acc[mi][j][half * 2 + 1] + b1;
                if (EPI == 0) {
                    int s = o >> 10;
                    int rem = o & 1023;
                    int hh = rem >> 6;
                    int d = rem & 63;
                    int bb = m >> 11;
                    int t = m & 2047;
                    size_t idx = (((size_t)(bb * HH + hh) * TT + t) * DH + d) >> 1;
                    __half2 hv(__float2half_rn(vx), __float2half_rn(vy));
                    if (s == 0)      ((__half2*)g_q_h)[idx] = hv;
                    else if (s == 1) ((__half2*)g_k_h)[idx] = hv;
                    else             ((__half2*)g_v_h)[idx] = hv;
                } else {
                    *(float2*)&Cout[(size_t)m * N + o] = make_float2(vx, vy);
                }
            }
        }
    }
}

// ---------------------------------------------------------------------------
// Flash attention: fp16 mma.sync, FMA fast-exp, 256 q-rows/CTA.
// 64-col KV tiles double-buffered; V natural layout + ldmatrix.trans.
// smem: QH 32K | 2 x (KH 8K | VH 8K) = 64KB
// ---------------------------------------------------------------------------
#define FQ_H  0
#define FBUF0 32768
#define FBSZ  16384
#define F_KH  0
#define F_VH  8192
#define FL_SMEM 65536

__launch_bounds__(256, 1)
__global__ void flash_mma() {
    extern __shared__ char fsm[];
    const uint32_t sb = smem_u32(fsm);
    const int tid = threadIdx.x;
    const int wid = tid >> 5;
    const int lane = tid & 31;
    const int b = blockIdx.y >> 4;
    const int h = blockIdx.y & 15;
    const int i0 = blockIdx.x * 256;

    const int a_row = (lane & 7) + ((lane >> 3) & 1) * 8;
    const int a_kc  = lane >> 4;
    const int b_row = ((lane >> 4) * 8) + (lane & 7);
    const int b_kc  = (lane >> 3) & 1;
    const int v_row = (lane & 7) + ((lane >> 3) & 1) * 8;
    const int v_dc  = (lane >> 4) * 8;

    const size_t qoff = (size_t)(b * HH + h) * TT * DH;
    const __half* Qh = g_q_h + qoff + (size_t)i0 * DH;
    const __half* Kh = g_k_h + qoff;
    const __half* Vh = g_v_h + qoff;
    const float* dec = g_decay + h * TT;

    gload_q256(Qh, sb + FQ_H, tid);
    CP_COMMIT();
    {
        const uint32_t d0 = sb + FBUF0;
        gload_kv64(Kh, d0 + F_KH, tid);
        gload_kv64(Vh, d0 + F_VH, tid);
        CP_COMMIT();
    }
    CP_WAIT1();               // Q landed
    __syncthreads();

    uint32_t qh[2][4][4];     // Q fragments persistent
#pragma unroll
    for (int blk = 0; blk < 2; blk++)
#pragma unroll
        for (int kt = 0; kt < 4; kt++) {
            uint32_t off = swz((wid * 32 + blk * 16 + a_row) * 128 + (kt * 2 + a_kc) * 16);
            ldmx4(qh[blk][kt], sb + FQ_H + off);
        }

    float O[2][8][4];
#pragma unroll
    for (int blk = 0; blk < 2; blk++)
#pragma unroll
        for (int j = 0; j < 8; j++)
#pragma unroll
            for (int q = 0; q < 4; q++) O[blk][j][q] = 0.f;
    float lsum[2][2] = {{0.f, 0.f}, {0.f, 0.f}};
    const float K1 = 0.125f * 1.44269504f;    // scale * log2(e)

    for (int c = 0; c < 32; c++) {            // 64-wide KV tiles
        CP_WAIT0();
        __syncthreads();

        if (c < 31) {
            const uint32_t dn = sb + FBUF0 + ((c + 1) & 1) * FBSZ;
            const size_t j1 = (size_t)(c + 1) * 64;
            gload_kv64(Kh + j1 * DH, dn + F_KH, tid);
            gload_kv64(Vh + j1 * DH, dn + F_VH, tid);
            CP_COMMIT();
        }

        const uint32_t cur = sb + FBUF0 + (c & 1) * FBSZ;
        const uint32_t sKh = cur + F_KH;
        const uint32_t sVh = cur + F_VH;
        const int j0 = c * 64;

        // S = Q K^T
        float s[2][8][4];
#pragma unroll
        for (int blk = 0; blk < 2; blk++)
#pragma unroll
            for (int j = 0; j < 8; j++)
#pragma unroll
                for (int q = 0; q < 4; q++) s[blk][j][q] = 0.f;
#pragma unroll
        for (int kt = 0; kt < 4; kt++) {
#pragma unroll
            for (int ng = 0; ng < 4; ng++) {
                uint32_t kb[4];
                uint32_t off = swz((ng * 16 + b_row) * 128 + (kt * 2 + b_kc) * 16);
                ldmx4(kb, sKh + off);
#pragma unroll
                for (int blk = 0; blk < 2; blk++) {
                    mma_f16(s[blk][2 * ng],     qh[blk][kt], kb[0], kb[1]);
                    mma_f16(s[blk][2 * ng + 1], qh[blk][kt], kb[2], kb[3]);
                }
            }
        }

        // p = exp2(s * scale*log2e * decay)
#pragma unroll
        for (int blk = 0; blk < 2; blk++) {
            const int r_lo = i0 + wid * 32 + blk * 16 + (lane >> 2);
#pragma unroll
            for (int j = 0; j < 8; j++) {
                int cbase = j0 + j * 8 + (lane & 3) * 2;
#pragma unroll
                for (int cc = 0; cc < 4; cc++) {
                    int rg = r_lo + ((cc >= 2) ? 8 : 0);
                    int cg = cbase + (cc & 1);
                    float dcy = __ldg(&dec[abs(rg - cg)]);
                    float p = fexp2(s[blk][j][cc] * dcy * K1);
                    s[blk][j][cc] = p;
                    lsum[blk][cc >> 1] += p;
                }
            }
        }

        // O += P V (P fp16 from registers; V via ldmatrix.trans)
#pragma unroll
        for (int kt = 0; kt < 4; kt++) {
            uint32_t ph[2][4];
#pragma unroll
            for (int blk = 0; blk < 2; blk++) {
                ph[blk][0] = pack16(s[blk][2 * kt][0],     s[blk][2 * kt][1]);
                ph[blk][1] = pack16(s[blk][2 * kt][2],     s[blk][2 * kt][3]);
                ph[blk][2] = pack16(s[blk][2 * kt + 1][0], s[blk][2 * kt + 1][1]);
                ph[blk][3] = pack16(s[blk][2 * kt + 1][2], s[blk][2 * kt + 1][3]);
            }
#pragma unroll
            for (int ng = 0; ng < 4; ng++) {
                uint32_t vh2[4];
                uint32_t off = swz((kt * 16 + v_row) * 128 + (ng * 16 + v_dc) * 2);
                ldmx4t(vh2, sVh + off);
#pragma unroll
                for (int blk = 0; blk < 2; blk++) {
                    mma_f16(O[blk][2 * ng],     ph[blk], vh2[0], vh2[1]);
                    mma_f16(O[blk][2 * ng + 1], ph[blk], vh2[2], vh2[3]);
                }
            }
        }
    }

#pragma unroll
    for (int blk = 0; blk < 2; blk++) {
        float l0 = lsum[blk][0], l1 = lsum[blk][1];
        l0 += __shfl_xor_sync(0xffffffffu, l0, 1);
        l0 += __shfl_xor_sync(0xffffffffu, l0, 2);
        l1 += __shfl_xor_sync(0xffffffffu, l1, 1);
        l1 += __shfl_xor_sync(0xffffffffu, l1, 2);
        const float inv0 = 1.f / l0;
        const float inv1 = 1.f / l1;
        const int r_lo = i0 + wid * 32 + blk * 16 + (lane >> 2);
#pragma unroll
        for (int j = 0; j < 8; j++) {
            int d = j * 8 + (lane & 3) * 2;
            size_t base0 = ((size_t)b * TT + (size_t)r_lo) * CC + h * DH + d;
            size_t base1 = base0 + 8 * CC;
            ((uint32_t*)g_ao_h)[base0 >> 1] = pack16(O[blk][j][0] * inv0, O[blk][j][1] * inv0);
            ((uint32_t*)g_ao_h)[base1 >> 1] = pack16(O[blk][j][2] * inv1, O[blk][j][3] * inv1);
        }
    }
}

// ---------------------------------------------------------------------------
extern "C" void kernel_launch(void* const* d_in, const int* in_sizes, int n_in,
                              void* d_out, int out_size) {
    const float* x = (const float*)d_in[0];
    const float* qkv_w = (const float*)d_in[1];
    const float* qkv_b = (const float*)d_in[2];
    const float* proj_w = (const float*)d_in[3];
    const float* proj_b = (const float*)d_in[4];
    const float* lambda_raw = (const float*)d_in[5];
    float* out = (float*)d_out;

    void *p_xh, *p_w1h, *p_w2h, *p_aoh;
    cudaGetSymbolAddress(&p_xh, g_x_h);
    cudaGetSymbolAddress(&p_w1h, g_w1_h);
    cudaGetSymbolAddress(&p_w2h, g_w2_h);
    cudaGetSymbolAddress(&p_aoh, g_ao_h);

    cudaFuncSetAttribute(flash_mma, cudaFuncAttributeMaxDynamicSharedMemorySize, FL_SMEM);
    cudaFuncSetAttribute(gemm_mma<0>, cudaFuncAttributeMaxDynamicSharedMemorySize, GEMM_SMEM);
    cudaFuncSetAttribute(gemm_mma<1>, cudaFuncAttributeMaxDynamicSharedMemorySize, GEMM_SMEM);

    decay_kernel<<<(HH * TT + 255) / 256, 256>>>(lambda_raw);

    conv_fp16<<<4194304 / 4 / 256, 256>>>(x, (__half*)p_xh, 4194304 / 4);
    conv_fp16<<<3145728 / 4 / 256, 256>>>(qkv_w, (__half*)p_w1h, 3145728 / 4);
    conv_fp16<<<1048576 / 4 / 256, 256>>>(proj_w, (__half*)p_w2h, 1048576 / 4);

    gemm_mma<0><<<dim3(3072 / 128, 4096 / 256), 256, GEMM_SMEM>>>(
        (const __half*)p_xh, (const __half*)p_w1h, qkv_b, nullptr, 3072);

    flash_mma<<<dim3(TT / 256, BB * HH), 256, FL_SMEM>>>();

    gemm_mma<1><<<dim3(1024 / 128, 4096 / 256), 256, GEMM_SMEM>>>(
        (const __half*)p_aoh, (const __half*)p_w2h, proj_b, out, 1024);
}

// round 12
// speedup vs baseline: 2.7528x; 1.2684x over previous
#include <cuda_runtime.h>
#include <cuda_fp16.h>
#include <math.h>
#include <stdint.h>

#define BB 2
#define TT 2048
#define CC 1024
#define HH 16
#define DH 64

// ---------------------------------------------------------------------------
// Scratch (device globals: allocation-free rule). Pure fp16 planes.
// ---------------------------------------------------------------------------
__device__ float g_decay[HH * TT];                 // [h][dist]
__device__ int   g_cut[HH];                        // first dist with decay < 1e-10
__device__ float g_sv[BB * HH * DH];               // column sums of V

__device__ __half g_q_h[4194304];                  // [b][h][t][d]
__device__ __half g_k_h[4194304];
__device__ __half g_v_h[4194304];
__device__ __half g_ao_h[4194304];

__device__ __half g_x_h[4194304];
__device__ __half g_w1_h[3145728];
__device__ __half g_w2_h[1048576];

// ---------------------------------------------------------------------------
// helpers
// ---------------------------------------------------------------------------
__device__ __forceinline__ uint32_t smem_u32(const void* p) {
    uint32_t a;
    asm("{ .reg .u64 t; cvta.to.shared.u64 t, %1; cvt.u32.u64 %0, t; }" : "=r"(a) : "l"(p));
    return a;
}
__device__ __forceinline__ uint32_t swz(uint32_t off) {     // 128B rows
    return off ^ ((off >> 3) & 0x70);
}
__device__ __forceinline__ void ldmx4(uint32_t* r, uint32_t addr) {
    asm volatile("ldmatrix.sync.aligned.m8n8.x4.shared.b16 {%0,%1,%2,%3}, [%4];"
                 : "=r"(r[0]), "=r"(r[1]), "=r"(r[2]), "=r"(r[3]) : "r"(addr));
}
__device__ __forceinline__ void ldmx4t(uint32_t* r, uint32_t addr) {
    asm volatile("ldmatrix.sync.aligned.m8n8.x4.trans.shared.b16 {%0,%1,%2,%3}, [%4];"
                 : "=r"(r[0]), "=r"(r[1]), "=r"(r[2]), "=r"(r[3]) : "r"(addr));
}
__device__ __forceinline__ void mma_f16(float* c, const uint32_t* a, uint32_t b0, uint32_t b1) {
    asm volatile("mma.sync.aligned.m16n8k16.row.col.f32.f16.f16.f32 "
                 "{%0,%1,%2,%3}, {%4,%5,%6,%7}, {%8,%9}, {%0,%1,%2,%3};"
                 : "+f"(c[0]), "+f"(c[1]), "+f"(c[2]), "+f"(c[3])
                 : "r"(a[0]), "r"(a[1]), "r"(a[2]), "r"(a[3]), "r"(b0), "r"(b1));
}
__device__ __forceinline__ void cpa16(uint32_t dst, const void* src) {
    asm volatile("cp.async.cg.shared.global [%0], [%1], 16;" :: "r"(dst), "l"(src));
}
#define CP_COMMIT() asm volatile("cp.async.commit_group;" ::: "memory")
#define CP_WAIT1()  asm volatile("cp.async.wait_group 1;" ::: "memory")
#define CP_WAIT0()  asm volatile("cp.async.wait_group 0;" ::: "memory")

// fast 2^y via FMA only (no MUFU)
__device__ __forceinline__ float fexp2(float y) {
    y = fminf(fmaxf(y, -120.f), 80.f);
    float z = y + 12582912.f;
    int iz = __float_as_int(z);
    float f = y - (z - 12582912.f);
    float p = 1.3333558e-3f;
    p = fmaf(p, f, 9.6181291e-3f);
    p = fmaf(p, f, 5.5504109e-2f);
    p = fmaf(p, f, 2.4022651e-1f);
    p = fmaf(p, f, 6.9314718e-1f);
    p = fmaf(p, f, 1.0f);
    return p * __int_as_float((iz + (127 - 0x4B400000)) << 23);
}
__device__ __forceinline__ uint32_t pack16(float x, float y) {
    __half hx = __float2half_rn(x), hy = __float2half_rn(y);
    return ((uint32_t)__half_as_ushort(hy) << 16) | (uint32_t)__half_as_ushort(hx);
}

// ---------------------------------------------------------------------------
__global__ void conv_fp16(const float* __restrict__ src, __half* __restrict__ hi, int n4) {
    int i = blockIdx.x * blockDim.x + threadIdx.x;
    if (i < n4) {
        float4 v = ((const float4*)src)[i];
        __half2* H = (__half2*)hi;
        H[i * 2]     = __half2(__float2half_rn(v.x), __float2half_rn(v.y));
        H[i * 2 + 1] = __half2(__float2half_rn(v.z), __float2half_rn(v.w));
    }
}

__global__ void decay_kernel(const float* __restrict__ lambda_raw) {
    int idx = blockIdx.x * blockDim.x + threadIdx.x;
    if (idx < HH * TT) {
        int h = idx / TT;
        int d = idx % TT;
        float lam = log1pf(expf(lambda_raw[h]));
        g_decay[idx] = expf(-lam * (float)d);
    }
}

// binary search first dist with decay < 1e-10 (decay monotone non-increasing)
__global__ void cut_kernel() {
    int h = threadIdx.x;
    if (h < HH) {
        const float* d = g_decay + h * TT;
        int lo = 0, hi = TT;          // invariant: all < lo have dec >= 1e-10... find first < thr
        while (lo < hi) {
            int mid = (lo + hi) >> 1;
            if (d[mid] < 1e-10f) hi = mid; else lo = mid + 1;
        }
        g_cut[h] = lo;                // dist >= lo  =>  decay < 1e-10  =>  p == 1.0f exactly
    }
}

// column sums of V: g_sv[(b*HH+h)*DH + d] = sum_t V[b][h][t][d]
__global__ void sumv_kernel() {
    __shared__ float red[4][DH];
    const int bh = blockIdx.x;
    const int d = threadIdx.x & 63;
    const int part = threadIdx.x >> 6;          // 0..3
    const __half* v = g_v_h + (size_t)bh * TT * DH;
    float s = 0.f;
    #pragma unroll 4
    for (int t = part * 512; t < (part + 1) * 512; t++)
        s += __half2float(v[(size_t)t * DH + d]);
    red[part][d] = s;
    __syncthreads();
    if (part == 0)
        g_sv[bh * DH + d] = red[0][d] + red[1][d] + red[2][d] + red[3][d];
}

// ---------------------------------------------------------------------------
// async tile loaders
// ---------------------------------------------------------------------------
__device__ __forceinline__ void gload_a256(const __half* __restrict__ g,
                                           uint32_t dst, int tid) {
#pragma unroll
    for (int i = 0; i < 8; i++) {
        int slot = tid + i * 256;
        int row = slot >> 3;
        int c16 = slot & 7;
        cpa16(dst + swz(row * 128 + c16 * 16), g + (size_t)row * 1024 + c16 * 8);
    }
}
__device__ __forceinline__ void gload_b128(const __half* __restrict__ g,
                                           uint32_t dst, int tid) {
#pragma unroll
    for (int i = 0; i < 4; i++) {
        int slot = tid + i * 256;
        int row = slot >> 3;
        int c16 = slot & 7;
        cpa16(dst + swz(row * 128 + c16 * 16), g + (size_t)row * 1024 + c16 * 8);
    }
}
__device__ __forceinline__ void gload_q256(const __half* __restrict__ g,
                                           uint32_t dst, int tid) {
#pragma unroll
    for (int i = 0; i < 8; i++) {
        int slot = tid + i * 256;
        int row = slot >> 3;
        int c16 = slot & 7;
        cpa16(dst + swz(row * 128 + c16 * 16), g + (size_t)row * 64 + c16 * 8);
    }
}
__device__ __forceinline__ void gload_kv64(const __half* __restrict__ g,
                                           uint32_t dst, int tid) {
#pragma unroll
    for (int i = 0; i < 2; i++) {
        int slot = tid + i * 256;
        int row = slot >> 3;
        int c16 = slot & 7;
        cpa16(dst + swz(row * 128 + c16 * 16), g + (size_t)row * 64 + c16 * 8);
    }
}

// ---------------------------------------------------------------------------
// fp16 mma.sync NT GEMM: C = A * B^T + bias. 256x128 CTA tile, BK=64,
// double-buffered. smem buf: AH 32K | BH 16K = 48KB; x2 = 96KB
// ---------------------------------------------------------------------------
#define GA_H 0
#define GB_H 32768
#define GBUF 49152
#define GEMM_SMEM 98304

template <int EPI>
__launch_bounds__(256, 1)
__global__ void gemm_mma(const __half* __restrict__ Ah, const __half* __restrict__ Bh,
                         const float* __restrict__ bias, float* __restrict__ Cout, int N) {
    extern __shared__ char smem[];
    const uint32_t sb = smem_u32(smem);
    const int tid = threadIdx.x;
    const int wid = tid >> 5;
    const int lane = tid & 31;
    const int wm = wid & 3;
    const int wn = wid >> 2;
    const int n0 = blockIdx.x * 128;
    const int m0 = blockIdx.y * 256;

    const int a_row = (lane & 7) + ((lane >> 3) & 1) * 8;
    const int a_kc  = lane >> 4;
    const int b_row = ((lane >> 4) * 8) + (lane & 7);
    const int b_kc  = (lane >> 3) & 1;

    const __half* Abase = Ah + (size_t)m0 * 1024;
    const __half* Bbase = Bh + (size_t)n0 * 1024;

    float acc[4][8][4];
#pragma unroll
    for (int i = 0; i < 4; i++)
#pragma unroll
        for (int j = 0; j < 8; j++)
#pragma unroll
            for (int q = 0; q < 4; q++) acc[i][j][q] = 0.f;

    gload_a256(Abase, sb + GA_H, tid);
    gload_b128(Bbase, sb + GB_H, tid);
    CP_COMMIT();

    for (int c = 0; c < 16; c++) {
        const uint32_t cur = (c & 1) ? GBUF : 0u;
        const uint32_t nxt = cur ^ GBUF;
        if (c < 15) {
            const size_t ka = (size_t)(c + 1) * 64;
            gload_a256(Abase + ka, sb + nxt + GA_H, tid);
            gload_b128(Bbase + ka, sb + nxt + GB_H, tid);
            CP_COMMIT();
            CP_WAIT1();
        } else {
            CP_WAIT0();
        }
        __syncthreads();

        const uint32_t sAh = sb + cur + GA_H;
        const uint32_t sBh = sb + cur + GB_H;
#pragma unroll
        for (int kt = 0; kt < 4; kt++) {
            uint32_t ah[4][4];
#pragma unroll
            for (int mi = 0; mi < 4; mi++) {
                uint32_t off = swz((wm * 64 + mi * 16 + a_row) * 128 + (kt * 2 + a_kc) * 16);
                ldmx4(ah[mi], sAh + off);
            }
#pragma unroll
            for (int ng = 0; ng < 4; ng++) {
                uint32_t bh[4];
                uint32_t off = swz((wn * 64 + ng * 16 + b_row) * 128 + (kt * 2 + b_kc) * 16);
                ldmx4(bh, sBh + off);
#pragma unroll
                for (int mi = 0; mi < 4; mi++) {
                    mma_f16(acc[mi][2 * ng],     ah[mi], bh[0], bh[1]);
                    mma_f16(acc[mi][2 * ng + 1], ah[mi], bh[2], bh[3]);
                }
            }
        }
        __syncthreads();
    }

#pragma unroll
    for (int mi = 0; mi < 4; mi++) {
#pragma unroll
        for (int j = 0; j < 8; j++) {
            int row = m0 + wm * 64 + mi * 16 + (lane >> 2);
            int o = n0 + wn * 64 + j * 8 + (lane & 3) * 2;
            float b0 = bias[o], b1 = bias[o + 1];
#pragma unroll
            for (int half = 0; half < 2; half++) {
                int m = row + half * 8;
                float vx = acc[mi][j][half * 2] + b0;
                float vy = acc[mi][j][half * 2 + 1] + b1;
                if (EPI == 0) {
                    int s = o >> 10;
                    int rem = o & 1023;
                    int hh = rem >> 6;
                    int d = rem & 63;
                    int bb = m >> 11;
                    int t = m & 2047;
                    size_t idx = (((size_t)(bb * HH + hh) * TT + t) * DH + d) >> 1;
                    __half2 hv(__float2half_rn(vx), __float2half_rn(vy));
                    if (s == 0)      ((__half2*)g_q_h)[idx] = hv;
                    else if (s == 1) ((__half2*)g_k_h)[idx] = hv;
                    else             ((__half2*)g_v_h)[idx] = hv;
                } else {
                    *(float2*)&Cout[(size_t)m * N + o] = make_float2(vx, vy);
                }
            }
        }
    }
}

// ---------------------------------------------------------------------------
// Flash attention, far-field factorized:
//   p_j = 1 + (p_j - 1);  (p_j - 1) == 0 exactly for dist >= cut.
//   O = SV + sum_near (p-1) V;  l = 2048 + sum_near (p-1).
// Only tiles with min-dist <= cut are processed.
// smem: QH 32K | 2 x (KH 8K | VH 8K) = 64KB
// ---------------------------------------------------------------------------
#define FQ_H  0
#define FBUF0 32768
#define FBSZ  16384
#define F_KH  0
#define F_VH  8192
#define FL_SMEM 65536

__launch_bounds__(256, 1)
__global__ void flash_mma() {
    extern __shared__ char fsm[];
    const uint32_t sb = smem_u32(fsm);
    const int tid = threadIdx.x;
    const int wid = tid >> 5;
    const int lane = tid & 31;
    const int b = blockIdx.y >> 4;
    const int h = blockIdx.y & 15;
    const int i0 = blockIdx.x * 256;

    const int a_row = (lane & 7) + ((lane >> 3) & 1) * 8;
    const int a_kc  = lane >> 4;
    const int b_row = ((lane >> 4) * 8) + (lane & 7);
    const int b_kc  = (lane >> 3) & 1;
    const int v_row = (lane & 7) + ((lane >> 3) & 1) * 8;
    const int v_dc  = (lane >> 4) * 8;

    const size_t qoff = (size_t)(b * HH + h) * TT * DH;
    const __half* Qh = g_q_h + qoff + (size_t)i0 * DH;
    const __half* Kh = g_k_h + qoff;
    const __half* Vh = g_v_h + qoff;
    const float* dec = g_decay + h * TT;

    // near-tile range from per-head cutoff
    const int cut = g_cut[h];
    int c_lo = i0 - cut;
    c_lo = (c_lo < 0) ? 0 : (c_lo >> 6);
    int c_hi = ((i0 + 255 + cut) >> 6) + 1;
    if (c_hi > TT / 64) c_hi = TT / 64;

    gload_q256(Qh, sb + FQ_H, tid);
    CP_COMMIT();
    {
        const uint32_t d0 = sb + FBUF0 + (c_lo & 1) * FBSZ;
        gload_kv64(Kh + (size_t)c_lo * 64 * DH, d0 + F_KH, tid);
        gload_kv64(Vh + (size_t)c_lo * 64 * DH, d0 + F_VH, tid);
        CP_COMMIT();
    }
    CP_WAIT1();               // Q landed
    __syncthreads();

    uint32_t qh[2][4][4];     // Q fragments persistent
#pragma unroll
    for (int blk = 0; blk < 2; blk++)
#pragma unroll
        for (int kt = 0; kt < 4; kt++) {
            uint32_t off = swz((wid * 32 + blk * 16 + a_row) * 128 + (kt * 2 + a_kc) * 16);
            ldmx4(qh[blk][kt], sb + FQ_H + off);
        }

    float O[2][8][4];
#pragma unroll
    for (int blk = 0; blk < 2; blk++)
#pragma unroll
        for (int j = 0; j < 8; j++)
#pragma unroll
            for (int q = 0; q < 4; q++) O[blk][j][q] = 0.f;
    float lsum[2][2] = {{0.f, 0.f}, {0.f, 0.f}};
    const float K1 = 0.125f * 1.44269504f;    // scale * log2(e)

    for (int c = c_lo; c < c_hi; c++) {       // near 64-wide KV tiles only
        CP_WAIT0();
        __syncthreads();

        if (c + 1 < c_hi) {
            const uint32_t dn = sb + FBUF0 + ((c + 1) & 1) * FBSZ;
            const size_t j1 = (size_t)(c + 1) * 64;
            gload_kv64(Kh + j1 * DH, dn + F_KH, tid);
            gload_kv64(Vh + j1 * DH, dn + F_VH, tid);
            CP_COMMIT();
        }

        const uint32_t cur = sb + FBUF0 + (c & 1) * FBSZ;
        const uint32_t sKh = cur + F_KH;
        const uint32_t sVh = cur + F_VH;
        const int j0 = c * 64;

        // S = Q K^T
        float s[2][8][4];
#pragma unroll
        for (int blk = 0; blk < 2; blk++)
#pragma unroll
            for (int j = 0; j < 8; j++)
#pragma unroll
                for (int q = 0; q < 4; q++) s[blk][j][q] = 0.f;
#pragma unroll
        for (int kt = 0; kt < 4; kt++) {
#pragma unroll
            for (int ng = 0; ng < 4; ng++) {
                uint32_t kb[4];
                uint32_t off = swz((ng * 16 + b_row) * 128 + (kt * 2 + b_kc) * 16);
                ldmx4(kb, sKh + off);
#pragma unroll
                for (int blk = 0; blk < 2; blk++) {
                    mma_f16(s[blk][2 * ng],     qh[blk][kt], kb[0], kb[1]);
                    mma_f16(s[blk][2 * ng + 1], qh[blk][kt], kb[2], kb[3]);
                }
            }
        }

        // (p - 1) = exp2(s * scale*log2e * decay) - 1  (exactly 0 for far pairs)
#pragma unroll
        for (int blk = 0; blk < 2; blk++) {
            const int r_lo = i0 + wid * 32 + blk * 16 + (lane >> 2);
#pragma unroll
            for (int j = 0; j < 8; j++) {
                int cbase = j0 + j * 8 + (lane & 3) * 2;
#pragma unroll
                for (int cc = 0; cc < 4; cc++) {
                    int rg = r_lo + ((cc >= 2) ? 8 : 0);
                    int cg = cbase + (cc & 1);
                    float dcy = __ldg(&dec[abs(rg - cg)]);
                    float pm1 = fexp2(s[blk][j][cc] * dcy * K1) - 1.0f;
                    s[blk][j][cc] = pm1;
                    lsum[blk][cc >> 1] += pm1;
                }
            }
        }

        // O += (P-1) V
#pragma unroll
        for (int kt = 0; kt < 4; kt++) {
            uint32_t ph[2][4];
#pragma unroll
            for (int blk = 0; blk < 2; blk++) {
                ph[blk][0] = pack16(s[blk][2 * kt][0],     s[blk][2 * kt][1]);
                ph[blk][1] = pack16(s[blk][2 * kt][2],     s[blk][2 * kt][3]);
                ph[blk][2] = pack16(s[blk][2 * kt + 1][0], s[blk][2 * kt + 1][1]);
                ph[blk][3] = pack16(s[blk][2 * kt + 1][2], s[blk][2 * kt + 1][3]);
            }
#pragma unroll
            for (int ng = 0; ng < 4; ng++) {
                uint32_t vh2[4];
                uint32_t off = swz((kt * 16 + v_row) * 128 + (ng * 16 + v_dc) * 2);
                ldmx4t(vh2, sVh + off);
#pragma unroll
                for (int blk = 0; blk < 2; blk++) {
                    mma_f16(O[blk][2 * ng],     ph[blk], vh2[0], vh2[1]);
                    mma_f16(O[blk][2 * ng + 1], ph[blk], vh2[2], vh2[3]);
                }
            }
        }
    }

    const float* SVp = g_sv + (size_t)(b * HH + h) * DH;
#pragma unroll
    for (int blk = 0; blk < 2; blk++) {
        float l0 = lsum[blk][0], l1 = lsum[blk][1];
        l0 += __shfl_xor_sync(0xffffffffu, l0, 1);
        l0 += __shfl_xor_sync(0xffffffffu, l0, 2);
        l1 += __shfl_xor_sync(0xffffffffu, l1, 1);
        l1 += __shfl_xor_sync(0xffffffffu, l1, 2);
        const float inv0 = 1.f / ((float)TT + l0);
        const float inv1 = 1.f / ((float)TT + l1);
        const int r_lo = i0 + wid * 32 + blk * 16 + (lane >> 2);
#pragma unroll
        for (int j = 0; j < 8; j++) {
            int d = j * 8 + (lane & 3) * 2;
            float2 sv = *(const float2*)&SVp[d];
            size_t base0 = ((size_t)b * TT + (size_t)r_lo) * CC + h * DH + d;
            size_t base1 = base0 + 8 * CC;
            ((uint32_t*)g_ao_h)[base0 >> 1] =
                pack16((O[blk][j][0] + sv.x) * inv0, (O[blk][j][1] + sv.y) * inv0);
            ((uint32_t*)g_ao_h)[base1 >> 1] =
                pack16((O[blk][j][2] + sv.x) * inv1, (O[blk][j][3] + sv.y) * inv1);
        }
    }
}

// ---------------------------------------------------------------------------
extern "C" void kernel_launch(void* const* d_in, const int* in_sizes, int n_in,
                              void* d_out, int out_size) {
    const float* x = (const float*)d_in[0];
    const float* qkv_w = (const float*)d_in[1];
    const float* qkv_b = (const float*)d_in[2];
    const float* proj_w = (const float*)d_in[3];
    const float* proj_b = (const float*)d_in[4];
    const float* lambda_raw = (const float*)d_in[5];
    float* out = (float*)d_out;

    void *p_xh, *p_w1h, *p_w2h, *p_aoh;
    cudaGetSymbolAddress(&p_xh, g_x_h);
    cudaGetSymbolAddress(&p_w1h, g_w1_h);
    cudaGetSymbolAddress(&p_w2h, g_w2_h);
    cudaGetSymbolAddress(&p_aoh, g_ao_h);

    cudaFuncSetAttribute(flash_mma, cudaFuncAttributeMaxDynamicSharedMemorySize, FL_SMEM);
    cudaFuncSetAttribute(gemm_mma<0>, cudaFuncAttributeMaxDynamicSharedMemorySize, GEMM_SMEM);
    cudaFuncSetAttribute(gemm_mma<1>, cudaFuncAttributeMaxDynamicSharedMemorySize, GEMM_SMEM);

    decay_kernel<<<(HH * TT + 255) / 256, 256>>>(lambda_raw);
    cut_kernel<<<1, HH>>>();

    conv_fp16<<<4194304 / 4 / 256, 256>>>(x, (__half*)p_xh, 4194304 / 4);
    conv_fp16<<<3145728 / 4 / 256, 256>>>(qkv_w, (__half*)p_w1h, 3145728 / 4);
    conv_fp16<<<1048576 / 4 / 256, 256>>>(proj_w, (__half*)p_w2h, 1048576 / 4);

    gemm_mma<0><<<dim3(3072 / 128, 4096 / 256), 256, GEMM_SMEM>>>(
        (const __half*)p_xh, (const __half*)p_w1h, qkv_b, nullptr, 3072);

    sumv_kernel<<<BB * HH, 256>>>();

    flash_mma<<<dim3(TT / 256, BB * HH), 256, FL_SMEM>>>();

    gemm_mma<1><<<dim3(1024 / 128, 4096 / 256), 256, GEMM_SMEM>>>(
        (const __half*)p_aoh, (const __half*)p_w2h, proj_b, out, 1024);
}

// round 13
// speedup vs baseline: 3.2809x; 1.1919x over previous
#include <cuda_runtime.h>
#include <cuda_fp16.h>
#include <math.h>
#include <stdint.h>

#define BB 2
#define TT 2048
#define CC 1024
#define HH 16
#define DH 64

// ---------------------------------------------------------------------------
__device__ float g_decay[HH * TT];                 // [h][dist]
__device__ int   g_cut[HH];                        // near-field cutoff per head
__device__ float g_sv[BB * HH * DH];               // column sums of V

__device__ __half g_q_h[4194304];                  // [b][h][t][d]
__device__ __half g_k_h[4194304];
__device__ __half g_v_h[4194304];
__device__ __half g_ao_h[4194304];

__device__ __half g_x_h[4194304];
__device__ __half g_w1_h[3145728];
__device__ __half g_w2_h[1048576];

// ---------------------------------------------------------------------------
__device__ __forceinline__ uint32_t smem_u32(const void* p) {
    uint32_t a;
    asm("{ .reg .u64 t; cvta.to.shared.u64 t, %1; cvt.u32.u64 %0, t; }" : "=r"(a) : "l"(p));
    return a;
}
__device__ __forceinline__ uint32_t swz(uint32_t off) {
    return off ^ ((off >> 3) & 0x70);
}
__device__ __forceinline__ void ldmx4(uint32_t* r, uint32_t addr) {
    asm volatile("ldmatrix.sync.aligned.m8n8.x4.shared.b16 {%0,%1,%2,%3}, [%4];"
                 : "=r"(r[0]), "=r"(r[1]), "=r"(r[2]), "=r"(r[3]) : "r"(addr));
}
__device__ __forceinline__ void ldmx4t(uint32_t* r, uint32_t addr) {
    asm volatile("ldmatrix.sync.aligned.m8n8.x4.trans.shared.b16 {%0,%1,%2,%3}, [%4];"
                 : "=r"(r[0]), "=r"(r[1]), "=r"(r[2]), "=r"(r[3]) : "r"(addr));
}
__device__ __forceinline__ void mma_f16(float* c, const uint32_t* a, uint32_t b0, uint32_t b1) {
    asm volatile("mma.sync.aligned.m16n8k16.row.col.f32.f16.f16.f32 "
                 "{%0,%1,%2,%3}, {%4,%5,%6,%7}, {%8,%9}, {%0,%1,%2,%3};"
                 : "+f"(c[0]), "+f"(c[1]), "+f"(c[2]), "+f"(c[3])
                 : "r"(a[0]), "r"(a[1]), "r"(a[2]), "r"(a[3]), "r"(b0), "r"(b1));
}
__device__ __forceinline__ void cpa16(uint32_t dst, const void* src) {
    asm volatile("cp.async.cg.shared.global [%0], [%1], 16;" :: "r"(dst), "l"(src));
}
#define CP_COMMIT() asm volatile("cp.async.commit_group;" ::: "memory")
#define CP_WAIT1()  asm volatile("cp.async.wait_group 1;" ::: "memory")
#define CP_WAIT0()  asm volatile("cp.async.wait_group 0;" ::: "memory")

__device__ __forceinline__ float fexp2(float y) {
    y = fminf(fmaxf(y, -120.f), 80.f);
    float z = y + 12582912.f;
    int iz = __float_as_int(z);
    float f = y - (z - 12582912.f);
    float p = 1.3333558e-3f;
    p = fmaf(p, f, 9.6181291e-3f);
    p = fmaf(p, f, 5.5504109e-2f);
    p = fmaf(p, f, 2.4022651e-1f);
    p = fmaf(p, f, 6.9314718e-1f);
    p = fmaf(p, f, 1.0f);
    return p * __int_as_float((iz + (127 - 0x4B400000)) << 23);
}
__device__ __forceinline__ uint32_t pack16(float x, float y) {
    __half hx = __float2half_rn(x), hy = __float2half_rn(y);
    return ((uint32_t)__half_as_ushort(hy) << 16) | (uint32_t)__half_as_ushort(hx);
}

// ---------------------------------------------------------------------------
// one fused conversion kernel for x, qkv_w, proj_w
// ---------------------------------------------------------------------------
#define CN1 1048576                    // x float4 count
#define CN2 (CN1 + 786432)             // + w1
#define CN3 (CN2 + 262144)             // + w2
__global__ void conv3(const float* __restrict__ x, const float* __restrict__ w1,
                      const float* __restrict__ w2) {
    int i = blockIdx.x * blockDim.x + threadIdx.x;
    const float* src;
    __half* dst;
    int off;
    if (i < CN1)      { src = x;  dst = g_x_h;  off = i; }
    else if (i < CN2) { src = w1; dst = g_w1_h; off = i - CN1; }
    else if (i < CN3) { src = w2; dst = g_w2_h; off = i - CN2; }
    else return;
    float4 v = ((const float4*)src)[off];
    __half2* H = (__half2*)dst;
    H[off * 2]     = __half2(__float2half_rn(v.x), __float2half_rn(v.y));
    H[off * 2 + 1] = __half2(__float2half_rn(v.z), __float2half_rn(v.w));
}

// decay table + analytic near-field cutoff (decay < 1e-5 beyond cut)
__global__ void decay_kernel(const float* __restrict__ lambda_raw) {
    int idx = blockIdx.x * blockDim.x + threadIdx.x;
    if (idx < HH * TT) {
        int h = idx / TT;
        int d = idx % TT;
        float lam = log1pf(expf(lambda_raw[h]));
        g_decay[idx] = expf(-lam * (float)d);
        if (d == 0) {
            int cut = (int)ceilf(11.512925f / lam) + 1;   // ln(1e5)/lam
            g_cut[h] = (cut > TT) ? TT : cut;
        }
    }
}

// column sums of V
__global__ void sumv_kernel() {
    __shared__ float red[4][DH];
    const int bh = blockIdx.x;
    const int d = threadIdx.x & 63;
    const int part = threadIdx.x >> 6;
    const __half* v = g_v_h + (size_t)bh * TT * DH;
    float s = 0.f;
    #pragma unroll 4
    for (int t = part * 512; t < (part + 1) * 512; t++)
        s += __half2float(v[(size_t)t * DH + d]);
    red[part][d] = s;
    __syncthreads();
    if (part == 0)
        g_sv[bh * DH + d] = red[0][d] + red[1][d] + red[2][d] + red[3][d];
}

// ---------------------------------------------------------------------------
// async tile loaders
// ---------------------------------------------------------------------------
__device__ __forceinline__ void gload_a256(const __half* __restrict__ g,
                                           uint32_t dst, int tid) {
#pragma unroll
    for (int i = 0; i < 8; i++) {
        int slot = tid + i * 256;
        int row = slot >> 3;
        int c16 = slot & 7;
        cpa16(dst + swz(row * 128 + c16 * 16), g + (size_t)row * 1024 + c16 * 8);
    }
}
__device__ __forceinline__ void gload_b128(const __half* __restrict__ g,
                                           uint32_t dst, int tid) {
#pragma unroll
    for (int i = 0; i < 4; i++) {
        int slot = tid + i * 256;
        int row = slot >> 3;
        int c16 = slot & 7;
        cpa16(dst + swz(row * 128 + c16 * 16), g + (size_t)row * 1024 + c16 * 8);
    }
}
__device__ __forceinline__ void gload_q128(const __half* __restrict__ g,
                                           uint32_t dst, int tid) {
#pragma unroll
    for (int i = 0; i < 4; i++) {
        int slot = tid + i * 256;
        int row = slot >> 3;
        int c16 = slot & 7;
        cpa16(dst + swz(row * 128 + c16 * 16), g + (size_t)row * 64 + c16 * 8);
    }
}
__device__ __forceinline__ void gload_kv64(const __half* __restrict__ g,
                                           uint32_t dst, int tid) {
#pragma unroll
    for (int i = 0; i < 2; i++) {
        int slot = tid + i * 256;
        int row = slot >> 3;
        int c16 = slot & 7;
        cpa16(dst + swz(row * 128 + c16 * 16), g + (size_t)row * 64 + c16 * 8);
    }
}

// ---------------------------------------------------------------------------
// fp16 mma.sync NT GEMM (unchanged from round 11/12)
// ---------------------------------------------------------------------------
#define GA_H 0
#define GB_H 32768
#define GBUF 49152
#define GEMM_SMEM 98304

template <int EPI>
__launch_bounds__(256, 1)
__global__ void gemm_mma(const __half* __restrict__ Ah, const __half* __restrict__ Bh,
                         const float* __restrict__ bias, float* __restrict__ Cout, int N) {
    extern __shared__ char smem[];
    const uint32_t sb = smem_u32(smem);
    const int tid = threadIdx.x;
    const int wid = tid >> 5;
    const int lane = tid & 31;
    const int wm = wid & 3;
    const int wn = wid >> 2;
    const int n0 = blockIdx.x * 128;
    const int m0 = blockIdx.y * 256;

    const int a_row = (lane & 7) + ((lane >> 3) & 1) * 8;
    const int a_kc  = lane >> 4;
    const int b_row = ((lane >> 4) * 8) + (lane & 7);
    const int b_kc  = (lane >> 3) & 1;

    const __half* Abase = Ah + (size_t)m0 * 1024;
    const __half* Bbase = Bh + (size_t)n0 * 1024;

    float acc[4][8][4];
#pragma unroll
    for (int i = 0; i < 4; i++)
#pragma unroll
        for (int j = 0; j < 8; j++)
#pragma unroll
            for (int q = 0; q < 4; q++) acc[i][j][q] = 0.f;

    gload_a256(Abase, sb + GA_H, tid);
    gload_b128(Bbase, sb + GB_H, tid);
    CP_COMMIT();

    for (int c = 0; c < 16; c++) {
        const uint32_t cur = (c & 1) ? GBUF : 0u;
        const uint32_t nxt = cur ^ GBUF;
        if (c < 15) {
            const size_t ka = (size_t)(c + 1) * 64;
            gload_a256(Abase + ka, sb + nxt + GA_H, tid);
            gload_b128(Bbase + ka, sb + nxt + GB_H, tid);
            CP_COMMIT();
            CP_WAIT1();
        } else {
            CP_WAIT0();
        }
        __syncthreads();

        const uint32_t sAh = sb + cur + GA_H;
        const uint32_t sBh = sb + cur + GB_H;
#pragma unroll
        for (int kt = 0; kt < 4; kt++) {
            uint32_t ah[4][4];
#pragma unroll
            for (int mi = 0; mi < 4; mi++) {
                uint32_t off = swz((wm * 64 + mi * 16 + a_row) * 128 + (kt * 2 + a_kc) * 16);
                ldmx4(ah[mi], sAh + off);
            }
#pragma unroll
            for (int ng = 0; ng < 4; ng++) {
                uint32_t bh[4];
                uint32_t off = swz((wn * 64 + ng * 16 + b_row) * 128 + (kt * 2 + b_kc) * 16);
                ldmx4(bh, sBh + off);
#pragma unroll
                for (int mi = 0; mi < 4; mi++) {
                    mma_f16(acc[mi][2 * ng],     ah[mi], bh[0], bh[1]);
                    mma_f16(acc[mi][2 * ng + 1], ah[mi], bh[2], bh[3]);
                }
            }
        }
        __syncthreads();
    }

#pragma unroll
    for (int mi = 0; mi < 4; mi++) {
#pragma unroll
        for (int j = 0; j < 8; j++) {
            int row = m0 + wm * 64 + mi * 16 + (lane >> 2);
            int o = n0 + wn * 64 + j * 8 + (lane & 3) * 2;
            float b0 = bias[o], b1 = bias[o + 1];
#pragma unroll
            for (int half = 0; half < 2; half++) {
                int m = row + half * 8;
                float vx = acc[mi][j][half * 2] + b0;
                float vy = acc[mi][j][half * 2 + 1] + b1;
                if (EPI == 0) {
                    int s = o >> 10;
                    int rem = o & 1023;
                    int hh = rem >> 6;
                    int d = rem & 63;
                    int bb = m >> 11;
                    int t = m & 2047;
                    size_t idx = (((size_t)(bb * HH + hh) * TT + t) * DH + d) >> 1;
                    __half2 hv(__float2half_rn(vx), __float2half_rn(vy));
                    if (s == 0)      ((__half2*)g_q_h)[idx] = hv;
                    else if (s == 1) ((__half2*)g_k_h)[idx] = hv;
                    else             ((__half2*)g_v_h)[idx] = hv;
                } else {
                    *(float2*)&Cout[(size_t)m * N + o] = make_float2(vx, vy);
                }
            }
        }
    }
}

// ---------------------------------------------------------------------------
// Flash attention, far-field factorized, 128 q-rows/CTA, cutoff=1e-5.
// smem: QH 16K | 2 x (KH 8K | VH 8K) = 48KB -> 2 CTAs/SM
// ---------------------------------------------------------------------------
#define FQ_H  0
#define FBUF0 16384
#define FBSZ  16384
#define F_KH  0
#define F_VH  8192
#define FL_SMEM 49152

__launch_bounds__(256, 2)
__global__ void flash_mma() {
    extern __shared__ char fsm[];
    const uint32_t sb = smem_u32(fsm);
    const int tid = threadIdx.x;
    const int wid = tid >> 5;
    const int lane = tid & 31;
    const int b = blockIdx.y >> 4;
    const int h = blockIdx.y & 15;
    const int i0 = blockIdx.x * 128;

    const int a_row = (lane & 7) + ((lane >> 3) & 1) * 8;
    const int a_kc  = lane >> 4;
    const int b_row = ((lane >> 4) * 8) + (lane & 7);
    const int b_kc  = (lane >> 3) & 1;
    const int v_row = (lane & 7) + ((lane >> 3) & 1) * 8;
    const int v_dc  = (lane >> 4) * 8;

    const size_t qoff = (size_t)(b * HH + h) * TT * DH;
    const __half* Qh = g_q_h + qoff + (size_t)i0 * DH;
    const __half* Kh = g_k_h + qoff;
    const __half* Vh = g_v_h + qoff;
    const float* dec = g_decay + h * TT;

    const int cut = g_cut[h];
    int c_lo = i0 - cut;
    c_lo = (c_lo < 0) ? 0 : (c_lo >> 6);
    int c_hi = ((i0 + 127 + cut) >> 6) + 1;
    if (c_hi > TT / 64) c_hi = TT / 64;

    gload_q128(Qh, sb + FQ_H, tid);
    CP_COMMIT();
    {
        const uint32_t d0 = sb + FBUF0 + (c_lo & 1) * FBSZ;
        gload_kv64(Kh + (size_t)c_lo * 64 * DH, d0 + F_KH, tid);
        gload_kv64(Vh + (size_t)c_lo * 64 * DH, d0 + F_VH, tid);
        CP_COMMIT();
    }
    CP_WAIT1();
    __syncthreads();

    uint32_t qh[4][4];
#pragma unroll
    for (int kt = 0; kt < 4; kt++) {
        uint32_t off = swz((wid * 16 + a_row) * 128 + (kt * 2 + a_kc) * 16);
        ldmx4(qh[kt], sb + FQ_H + off);
    }

    float O[8][4];
#pragma unroll
    for (int j = 0; j < 8; j++)
#pragma unroll
        for (int q = 0; q < 4; q++) O[j][q] = 0.f;
    float lsum0 = 0.f, lsum1 = 0.f;
    const float K1 = 0.125f * 1.44269504f;
    const int r_lo = i0 + wid * 16 + (lane >> 2);

    for (int c = c_lo; c < c_hi; c++) {
        CP_WAIT0();
        __syncthreads();

        if (c + 1 < c_hi) {
            const uint32_t dn = sb + FBUF0 + ((c + 1) & 1) * FBSZ;
            const size_t j1 = (size_t)(c + 1) * 64;
            gload_kv64(Kh + j1 * DH, dn + F_KH, tid);
            gload_kv64(Vh + j1 * DH, dn + F_VH, tid);
            CP_COMMIT();
        }

        const uint32_t cur = sb + FBUF0 + (c & 1) * FBSZ;
        const uint32_t sKh = cur + F_KH;
        const uint32_t sVh = cur + F_VH;
        const int j0 = c * 64;

        // S = Q K^T
        float s[8][4];
#pragma unroll
        for (int j = 0; j < 8; j++)
#pragma unroll
            for (int q = 0; q < 4; q++) s[j][q] = 0.f;
#pragma unroll
        for (int kt = 0; kt < 4; kt++) {
#pragma unroll
            for (int ng = 0; ng < 4; ng++) {
                uint32_t kb[4];
                uint32_t off = swz((ng * 16 + b_row) * 128 + (kt * 2 + b_kc) * 16);
                ldmx4(kb, sKh + off);
                mma_f16(s[2 * ng],     qh[kt], kb[0], kb[1]);
                mma_f16(s[2 * ng + 1], qh[kt], kb[2], kb[3]);
            }
        }

        // (p - 1); == 0 for far pairs
#pragma unroll
        for (int j = 0; j < 8; j++) {
            int cbase = j0 + j * 8 + (lane & 3) * 2;
#pragma unroll
            for (int cc = 0; cc < 4; cc++) {
                int rg = r_lo + ((cc >= 2) ? 8 : 0);
                int cg = cbase + (cc & 1);
                float dcy = __ldg(&dec[abs(rg - cg)]);
                float pm1 = fexp2(s[j][cc] * dcy * K1) - 1.0f;
                s[j][cc] = pm1;
                if (cc < 2) lsum0 += pm1; else lsum1 += pm1;
            }
        }

        // O += (P-1) V
#pragma unroll
        for (int kt = 0; kt < 4; kt++) {
            uint32_t ph[4];
            ph[0] = pack16(s[2 * kt][0],     s[2 * kt][1]);
            ph[1] = pack16(s[2 * kt][2],     s[2 * kt][3]);
            ph[2] = pack16(s[2 * kt + 1][0], s[2 * kt + 1][1]);
            ph[3] = pack16(s[2 * kt + 1][2], s[2 * kt + 1][3]);
#pragma unroll
            for (int ng = 0; ng < 4; ng++) {
                uint32_t vh2[4];
                uint32_t off = swz((kt * 16 + v_row) * 128 + (ng * 16 + v_dc) * 2);
                ldmx4t(vh2, sVh + off);
                mma_f16(O[2 * ng],     ph, vh2[0], vh2[1]);
                mma_f16(O[2 * ng + 1], ph, vh2[2], vh2[3]);
            }
        }
    }

    const float* SVp = g_sv + (size_t)(b * HH + h) * DH;
    lsum0 += __shfl_xor_sync(0xffffffffu, lsum0, 1);
    lsum0 += __shfl_xor_sync(0xffffffffu, lsum0, 2);
    lsum1 += __shfl_xor_sync(0xffffffffu, lsum1, 1);
    lsum1 += __shfl_xor_sync(0xffffffffu, lsum1, 2);
    const float inv0 = 1.f / ((float)TT + lsum0);
    const float inv1 = 1.f / ((float)TT + lsum1);

#pragma unroll
    for (int j = 0; j < 8; j++) {
        int d = j * 8 + (lane & 3) * 2;
        float2 sv = *(const float2*)&SVp[d];
        size_t base0 = ((size_t)b * TT + (size_t)r_lo) * CC + h * DH + d;
        size_t base1 = base0 + 8 * CC;
        ((uint32_t*)g_ao_h)[base0 >> 1] =
            pack16((O[j][0] + sv.x) * inv0, (O[j][1] + sv.y) * inv0);
        ((uint32_t*)g_ao_h)[base1 >> 1] =
            pack16((O[j][2] + sv.x) * inv1, (O[j][3] + sv.y) * inv1);
    }
}

// ---------------------------------------------------------------------------
extern "C" void kernel_launch(void* const* d_in, const int* in_sizes, int n_in,
                              void* d_out, int out_size) {
    const float* x = (const float*)d_in[0];
    const float* qkv_w = (const float*)d_in[1];
    const float* qkv_b = (const float*)d_in[2];
    const float* proj_w = (const float*)d_in[3];
    const float* proj_b = (const float*)d_in[4];
    const float* lambda_raw = (const float*)d_in[5];
    float* out = (float*)d_out;

    void *p_xh, *p_w1h, *p_w2h, *p_aoh;
    cudaGetSymbolAddress(&p_xh, g_x_h);
    cudaGetSymbolAddress(&p_w1h, g_w1_h);
    cudaGetSymbolAddress(&p_w2h, g_w2_h);
    cudaGetSymbolAddress(&p_aoh, g_ao_h);

    cudaFuncSetAttribute(flash_mma, cudaFuncAttributeMaxDynamicSharedMemorySize, FL_SMEM);
    cudaFuncSetAttribute(gemm_mma<0>, cudaFuncAttributeMaxDynamicSharedMemorySize, GEMM_SMEM);
    cudaFuncSetAttribute(gemm_mma<1>, cudaFuncAttributeMaxDynamicSharedMemorySize, GEMM_SMEM);

    decay_kernel<<<(HH * TT + 255) / 256, 256>>>(lambda_raw);
    conv3<<<CN3 / 256, 256>>>(x, qkv_w, proj_w);

    gemm_mma<0><<<dim3(3072 / 128, 4096 / 256), 256, GEMM_SMEM>>>(
        (const __half*)p_xh, (const __half*)p_w1h, qkv_b, nullptr, 3072);

    sumv_kernel<<<BB * HH, 256>>>();

    flash_mma<<<dim3(TT / 128, BB * HH), 256, FL_SMEM>>>();

    gemm_mma<1><<<dim3(1024 / 128, 4096 / 256), 256, GEMM_SMEM>>>(
        (const __half*)p_aoh, (const __half*)p_w2h, proj_b, out, 1024);
}

// round 15
// speedup vs baseline: 3.8950x; 1.1872x over previous
#include <cuda_runtime.h>
#include <cuda_fp16.h>
#include <math.h>
#include <stdint.h>

#define BB 2
#define TT 2048
#define CC 1024
#define HH 16
#define DH 64

// ---------------------------------------------------------------------------
__device__ float g_decay[HH * TT];                 // [h][dist]
__device__ int   g_cut[HH];                        // near-field cutoff per head
__device__ float g_sv[BB * HH * DH];               // column sums of V

__device__ __half g_q_h[4194304];                  // [b][h][t][d]
__device__ __half g_k_h[4194304];
__device__ __half g_v_h[4194304];
__device__ __half g_ao_h[4194304];

__device__ __half g_x_h[4194304];
__device__ __half g_w1_h[3145728];
__device__ __half g_w2_h[1048576];

// ---------------------------------------------------------------------------
__device__ __forceinline__ uint32_t smem_u32(const void* p) {
    uint32_t a;
    asm("{ .reg .u64 t; cvta.to.shared.u64 t, %1; cvt.u32.u64 %0, t; }" : "=r"(a) : "l"(p));
    return a;
}
__device__ __forceinline__ uint32_t swz(uint32_t off) {
    return off ^ ((off >> 3) & 0x70);
}
__device__ __forceinline__ void ldmx4(uint32_t* r, uint32_t addr) {
    asm volatile("ldmatrix.sync.aligned.m8n8.x4.shared.b16 {%0,%1,%2,%3}, [%4];"
                 : "=r"(r[0]), "=r"(r[1]), "=r"(r[2]), "=r"(r[3]) : "r"(addr));
}
__device__ __forceinline__ void ldmx4t(uint32_t* r, uint32_t addr) {
    asm volatile("ldmatrix.sync.aligned.m8n8.x4.trans.shared.b16 {%0,%1,%2,%3}, [%4];"
                 : "=r"(r[0]), "=r"(r[1]), "=r"(r[2]), "=r"(r[3]) : "r"(addr));
}
__device__ __forceinline__ void mma_f16(float* c, const uint32_t* a, uint32_t b0, uint32_t b1) {
    asm volatile("mma.sync.aligned.m16n8k16.row.col.f32.f16.f16.f32 "
                 "{%0,%1,%2,%3}, {%4,%5,%6,%7}, {%8,%9}, {%0,%1,%2,%3};"
                 : "+f"(c[0]), "+f"(c[1]), "+f"(c[2]), "+f"(c[3])
                 : "r"(a[0]), "r"(a[1]), "r"(a[2]), "r"(a[3]), "r"(b0), "r"(b1));
}
__device__ __forceinline__ void cpa16(uint32_t dst, const void* src) {
    asm volatile("cp.async.cg.shared.global [%0], [%1], 16;" :: "r"(dst), "l"(src));
}
#define CP_COMMIT() asm volatile("cp.async.commit_group;" ::: "memory")
#define CP_WAIT1()  asm volatile("cp.async.wait_group 1;" ::: "memory")
#define CP_WAIT0()  asm volatile("cp.async.wait_group 0;" ::: "memory")

__device__ __forceinline__ float fexp2(float y) {
    y = fminf(fmaxf(y, -120.f), 80.f);
    float z = y + 12582912.f;
    int iz = __float_as_int(z);
    float f = y - (z - 12582912.f);
    float p = 1.3333558e-3f;
    p = fmaf(p, f, 9.6181291e-3f);
    p = fmaf(p, f, 5.5504109e-2f);
    p = fmaf(p, f, 2.4022651e-1f);
    p = fmaf(p, f, 6.9314718e-1f);
    p = fmaf(p, f, 1.0f);
    return p * __int_as_float((iz + (127 - 0x4B400000)) << 23);
}
__device__ __forceinline__ uint32_t pack16(float x, float y) {
    __half hx = __float2half_rn(x), hy = __float2half_rn(y);
    return ((uint32_t)__half_as_ushort(hy) << 16) | (uint32_t)__half_as_ushort(hx);
}

// ---------------------------------------------------------------------------
// one fused conversion kernel for x, qkv_w, proj_w
// ---------------------------------------------------------------------------
#define CN1 1048576                    // x float4 count
#define CN2 (CN1 + 786432)             // + w1
#define CN3 (CN2 + 262144)             // + w2
__global__ void conv3(const float* __restrict__ x, const float* __restrict__ w1,
                      const float* __restrict__ w2) {
    int i = blockIdx.x * blockDim.x + threadIdx.x;
    const float* src;
    __half* dst;
    int off;
    if (i < CN1)      { src = x;  dst = g_x_h;  off = i; }
    else if (i < CN2) { src = w1; dst = g_w1_h; off = i - CN1; }
    else if (i < CN3) { src = w2; dst = g_w2_h; off = i - CN2; }
    else return;
    float4 v = ((const float4*)src)[off];
    __half2* H = (__half2*)dst;
    H[off * 2]     = __half2(__float2half_rn(v.x), __float2half_rn(v.y));
    H[off * 2 + 1] = __half2(__float2half_rn(v.z), __float2half_rn(v.w));
}

// decay table + analytic cutoff + zero g_sv
__global__ void decay_kernel(const float* __restrict__ lambda_raw) {
    int idx = blockIdx.x * blockDim.x + threadIdx.x;
    if (idx < BB * HH * DH) g_sv[idx] = 0.f;
    if (idx < HH * TT) {
        int h = idx / TT;
        int d = idx % TT;
        float lam = log1pf(expf(lambda_raw[h]));
        g_decay[idx] = expf(-lam * (float)d);
        if (d == 0) {
            int cut = (int)ceilf(11.512925f / lam) + 1;   // ln(1e5)/lam
            g_cut[h] = (cut > TT) ? TT : cut;
        }
    }
}

// column sums of V: grid (BB*HH, 8), each block sums 256 t-rows, atomicAdd.
__global__ void sumv_kernel() {
    __shared__ float red[8][DH];
    const int bh = blockIdx.x;
    const int seg = blockIdx.y;                  // 0..7: rows [seg*256, seg*256+256)
    const int d2 = threadIdx.x & 31;             // half2 column index (0..31)
    const int part = threadIdx.x >> 5;           // 0..7 -> 32 rows each
    const __half2* v = (const __half2*)(g_v_h + (size_t)bh * TT * DH);
    float sx = 0.f, sy = 0.f;
    const int t0 = seg * 256 + part * 32;
    #pragma unroll 8
    for (int t = t0; t < t0 + 32; t++) {
        __half2 hv = v[(size_t)t * 32 + d2];
        float2 f = __half22float2(hv);
        sx += f.x; sy += f.y;
    }
    red[part][d2 * 2]     = sx;
    red[part][d2 * 2 + 1] = sy;
    __syncthreads();
    if (part == 0) {
        float rx = 0.f, ry = 0.f;
        #pragma unroll
        for (int p = 0; p < 8; p++) {
            rx += red[p][d2 * 2];
            ry += red[p][d2 * 2 + 1];
        }
        atomicAdd(&g_sv[bh * DH + d2 * 2], rx);
        atomicAdd(&g_sv[bh * DH + d2 * 2 + 1], ry);
    }
}

// ---------------------------------------------------------------------------
// async tile loaders
// ---------------------------------------------------------------------------
__device__ __forceinline__ void gload_a256(const __half* __restrict__ g,
                                           uint32_t dst, int tid) {
#pragma unroll
    for (int i = 0; i < 8; i++) {
        int slot = tid + i * 256;
        int row = slot >> 3;
        int c16 = slot & 7;
        cpa16(dst + swz(row * 128 + c16 * 16), g + (size_t)row * 1024 + c16 * 8);
    }
}
__device__ __forceinline__ void gload_b128(const __half* __restrict__ g,
                                           uint32_t dst, int tid) {
#pragma unroll
    for (int i = 0; i < 4; i++) {
        int slot = tid + i * 256;
        int row = slot >> 3;
        int c16 = slot & 7;
        cpa16(dst + swz(row * 128 + c16 * 16), g + (size_t)row * 1024 + c16 * 8);
    }
}
__device__ __forceinline__ void gload_q128(const __half* __restrict__ g,
                                           uint32_t dst, int tid) {
#pragma unroll
    for (int i = 0; i < 4; i++) {
        int slot = tid + i * 256;
        int row = slot >> 3;
        int c16 = slot & 7;
        cpa16(dst + swz(row * 128 + c16 * 16), g + (size_t)row * 64 + c16 * 8);
    }
}
__device__ __forceinline__ void gload_kv64(const __half* __restrict__ g,
                                           uint32_t dst, int tid) {
#pragma unroll
    for (int i = 0; i < 2; i++) {
        int slot = tid + i * 256;
        int row = slot >> 3;
        int c16 = slot & 7;
        cpa16(dst + swz(row * 128 + c16 * 16), g + (size_t)row * 64 + c16 * 8);
    }
}

// ---------------------------------------------------------------------------
// fp16 mma.sync NT GEMM (unchanged)
// ---------------------------------------------------------------------------
#define GA_H 0
#define GB_H 32768
#define GBUF 49152
#define GEMM_SMEM 98304

template <int EPI>
__launch_bounds__(256, 1)
__global__ void gemm_mma(const __half* __restrict__ Ah, const __half* __restrict__ Bh,
                         const float* __restrict__ bias, float* __restrict__ Cout, int N) {
    extern __shared__ char smem[];
    const uint32_t sb = smem_u32(smem);
    const int tid = threadIdx.x;
    const int wid = tid >> 5;
    const int lane = tid & 31;
    const int wm = wid & 3;
    const int wn = wid >> 2;
    const int n0 = blockIdx.x * 128;
    const int m0 = blockIdx.y * 256;

    const int a_row = (lane & 7) + ((lane >> 3) & 1) * 8;
    const int a_kc  = lane >> 4;
    const int b_row = ((lane >> 4) * 8) + (lane & 7);
    const int b_kc  = (lane >> 3) & 1;

    const __half* Abase = Ah + (size_t)m0 * 1024;
    const __half* Bbase = Bh + (size_t)n0 * 1024;

    float acc[4][8][4];
#pragma unroll
    for (int i = 0; i < 4; i++)
#pragma unroll
        for (int j = 0; j < 8; j++)
#pragma unroll
            for (int q = 0; q < 4; q++) acc[i][j][q] = 0.f;

    gload_a256(Abase, sb + GA_H, tid);
    gload_b128(Bbase, sb + GB_H, tid);
    CP_COMMIT();

    for (int c = 0; c < 16; c++) {
        const uint32_t cur = (c & 1) ? GBUF : 0u;
        const uint32_t nxt = cur ^ GBUF;
        if (c < 15) {
            const size_t ka = (size_t)(c + 1) * 64;
            gload_a256(Abase + ka, sb + nxt + GA_H, tid);
            gload_b128(Bbase + ka, sb + nxt + GB_H, tid);
            CP_COMMIT();
            CP_WAIT1();
        } else {
            CP_WAIT0();
        }
        __syncthreads();

        const uint32_t sAh = sb + cur + GA_H;
        const uint32_t sBh = sb + cur + GB_H;
#pragma unroll
        for (int kt = 0; kt < 4; kt++) {
            uint32_t ah[4][4];
#pragma unroll
            for (int mi = 0; mi < 4; mi++) {
                uint32_t off = swz((wm * 64 + mi * 16 + a_row) * 128 + (kt * 2 + a_kc) * 16);
                ldmx4(ah[mi], sAh + off);
            }
#pragma unroll
            for (int ng = 0; ng < 4; ng++) {
                uint32_t bh[4];
                uint32_t off = swz((wn * 64 + ng * 16 + b_row) * 128 + (kt * 2 + b_kc) * 16);
                ldmx4(bh, sBh + off);
#pragma unroll
                for (int mi = 0; mi < 4; mi++) {
                    mma_f16(acc[mi][2 * ng],     ah[mi], bh[0], bh[1]);
                    mma_f16(acc[mi][2 * ng + 1], ah[mi], bh[2], bh[3]);
                }
            }
        }
        __syncthreads();
    }

#pragma unroll
    for (int mi = 0; mi < 4; mi++) {
#pragma unroll
        for (int j = 0; j < 8; j++) {
            int row = m0 + wm * 64 + mi * 16 + (lane >> 2);
            int o = n0 + wn * 64 + j * 8 + (lane & 3) * 2;
            float b0 = bias[o], b1 = bias[o + 1];
#pragma unroll
            for (int half = 0; half < 2; half++) {
                int m = row + half * 8;
                float vx = acc[mi][j][half * 2] + b0;
                float vy = acc[mi][j][half * 2 + 1] + b1;
                if (EPI == 0) {
                    int s = o >> 10;
                    int rem = o & 1023;
                    int hh = rem >> 6;
                    int d = rem & 63;
                    int bb = m >> 11;
                    int t = m & 2047;
                    size_t idx = (((size_t)(bb * HH + hh) * TT + t) * DH + d) >> 1;
                    __half2 hv(__float2half_rn(vx), __float2half_rn(vy));
                    if (s == 0)      ((__half2*)g_q_h)[idx] = hv;
                    else if (s == 1) ((__half2*)g_k_h)[idx] = hv;
                    else             ((__half2*)g_v_h)[idx] = hv;
                } else {
                    *(float2*)&Cout[(size_t)m * N + o] = make_float2(vx, vy);
                }
            }
        }
    }
}

// ---------------------------------------------------------------------------
// Flash attention, far-field factorized, 128 q-rows/CTA (unchanged)
// ---------------------------------------------------------------------------
#define FQ_H  0
#define FBUF0 16384
#define FBSZ  16384
#define F_KH  0
#define F_VH  8192
#define FL_SMEM 49152

__launch_bounds__(256, 2)
__global__ void flash_mma() {
    extern __shared__ char fsm[];
    const uint32_t sb = smem_u32(fsm);
    const int tid = threadIdx.x;
    const int wid = tid >> 5;
    const int lane = tid & 31;
    const int b = blockIdx.y >> 4;
    const int h = blockIdx.y & 15;
    const int i0 = blockIdx.x * 128;

    const int a_row = (lane & 7) + ((lane >> 3) & 1) * 8;
    const int a_kc  = lane >> 4;
    const int b_row = ((lane >> 4) * 8) + (lane & 7);
    const int b_kc  = (lane >> 3) & 1;
    const int v_row = (lane & 7) + ((lane >> 3) & 1) * 8;
    const int v_dc  = (lane >> 4) * 8;

    const size_t qoff = (size_t)(b * HH + h) * TT * DH;
    const __half* Qh = g_q_h + qoff + (size_t)i0 * DH;
    const __half* Kh = g_k_h + qoff;
    const __half* Vh = g_v_h + qoff;
    const float* dec = g_decay + h * TT;

    const int cut = g_cut[h];
    int c_lo = i0 - cut;
    c_lo = (c_lo < 0) ? 0 : (c_lo >> 6);
    int c_hi = ((i0 + 127 + cut) >> 6) + 1;
    if (c_hi > TT / 64) c_hi = TT / 64;

    gload_q128(Qh, sb + FQ_H, tid);
    CP_COMMIT();
    {
        const uint32_t d0 = sb + FBUF0 + (c_lo & 1) * FBSZ;
        gload_kv64(Kh + (size_t)c_lo * 64 * DH, d0 + F_KH, tid);
        gload_kv64(Vh + (size_t)c_lo * 64 * DH, d0 + F_VH, tid);
        CP_COMMIT();
    }
    CP_WAIT1();
    __syncthreads();

    uint32_t qh[4][4];
#pragma unroll
    for (int kt = 0; kt < 4; kt++) {
        uint32_t off = swz((wid * 16 + a_row) * 128 + (kt * 2 + a_kc) * 16);
        ldmx4(qh[kt], sb + FQ_H + off);
    }

    float O[8][4];
#pragma unroll
    for (int j = 0; j < 8; j++)
#pragma unroll
        for (int q = 0; q < 4; q++) O[j][q] = 0.f;
    float lsum0 = 0.f, lsum1 = 0.f;
    const float K1 = 0.125f * 1.44269504f;
    const int r_lo = i0 + wid * 16 + (lane >> 2);

    for (int c = c_lo; c < c_hi; c++) {
        CP_WAIT0();
        __syncthreads();

        if (c + 1 < c_hi) {
            const uint32_t dn = sb + FBUF0 + ((c + 1) & 1) * FBSZ;
            const size_t j1 = (size_t)(c + 1) * 64;
            gload_kv64(Kh + j1 * DH, dn + F_KH, tid);
            gload_kv64(Vh + j1 * DH, dn + F_VH, tid);
            CP_COMMIT();
        }

        const uint32_t cur = sb + FBUF0 + (c & 1) * FBSZ;
        const uint32_t sKh = cur + F_KH;
        const uint32_t sVh = cur + F_VH;
        const int j0 = c * 64;

        float s[8][4];
#pragma unroll
        for (int j = 0; j < 8; j++)
#pragma unroll
            for (int q = 0; q < 4; q++) s[j][q] = 0.f;
#pragma unroll
        for (int kt = 0; kt < 4; kt++) {
#pragma unroll
            for (int ng = 0; ng < 4; ng++) {
                uint32_t kb[4];
                uint32_t off = swz((ng * 16 + b_row) * 128 + (kt * 2 + b_kc) * 16);
                ldmx4(kb, sKh + off);
                mma_f16(s[2 * ng],     qh[kt], kb[0], kb[1]);
                mma_f16(s[2 * ng + 1], qh[kt], kb[2], kb[3]);
            }
        }

#pragma unroll
        for (int j = 0; j < 8; j++) {
            int cbase = j0 + j * 8 + (lane & 3) * 2;
#pragma unroll
            for (int cc = 0; cc < 4; cc++) {
                int rg = r_lo + ((cc >= 2) ? 8 : 0);
                int cg = cbase + (cc & 1);
                float dcy = __ldg(&dec[abs(rg - cg)]);
                float pm1 = fexp2(s[j][cc] * dcy * K1) - 1.0f;
                s[j][cc] = pm1;
                if (cc < 2) lsum0 += pm1; else lsum1 += pm1;
            }
        }

#pragma unroll
        for (int kt = 0; kt < 4; kt++) {
            uint32_t ph[4];
            ph[0] = pack16(s[2 * kt][0],     s[2 * kt][1]);
            ph[1] = pack16(s[2 * kt][2],     s[2 * kt][3]);
            ph[2] = pack16(s[2 * kt + 1][0], s[2 * kt + 1][1]);
            ph[3] = pack16(s[2 * kt + 1][2], s[2 * kt + 1][3]);
#pragma unroll
            for (int ng = 0; ng < 4; ng++) {
                uint32_t vh2[4];
                uint32_t off = swz((kt * 16 + v_row) * 128 + (ng * 16 + v_dc) * 2);
                ldmx4t(vh2, sVh + off);
                mma_f16(O[2 * ng],     ph, vh2[0], vh2[1]);
                mma_f16(O[2 * ng + 1], ph, vh2[2], vh2[3]);
            }
        }
    }

    const float* SVp = g_sv + (size_t)(b * HH + h) * DH;
    lsum0 += __shfl_xor_sync(0xffffffffu, lsum0, 1);
    lsum0 += __shfl_xor_sync(0xffffffffu, lsum0, 2);
    lsum1 += __shfl_xor_sync(0xffffffffu, lsum1, 1);
    lsum1 += __shfl_xor_sync(0xffffffffu, lsum1, 2);
    const float inv0 = 1.f / ((float)TT + lsum0);
    const float inv1 = 1.f / ((float)TT + lsum1);

#pragma unroll
    for (int j = 0; j < 8; j++) {
        int d = j * 8 + (lane & 3) * 2;
        float2 sv = *(const float2*)&SVp[d];
        size_t base0 = ((size_t)b * TT + (size_t)r_lo) * CC + h * DH + d;
        size_t base1 = base0 + 8 * CC;
        ((uint32_t*)g_ao_h)[base0 >> 1] =
            pack16((O[j][0] + sv.x) * inv0, (O[j][1] + sv.y) * inv0);
        ((uint32_t*)g_ao_h)[base1 >> 1] =
            pack16((O[j][2] + sv.x) * inv1, (O[j][3] + sv.y) * inv1);
    }
}

// ---------------------------------------------------------------------------
extern "C" void kernel_launch(void* const* d_in, const int* in_sizes, int n_in,
                              void* d_out, int out_size) {
    const float* x = (const float*)d_in[0];
    const float* qkv_w = (const float*)d_in[1];
    const float* qkv_b = (const float*)d_in[2];
    const float* proj_w = (const float*)d_in[3];
    const float* proj_b = (const float*)d_in[4];
    const float* lambda_raw = (const float*)d_in[5];
    float* out = (float*)d_out;

    void *p_xh, *p_w1h, *p_w2h, *p_aoh;
    cudaGetSymbolAddress(&p_xh, g_x_h);
    cudaGetSymbolAddress(&p_w1h, g_w1_h);
    cudaGetSymbolAddress(&p_w2h, g_w2_h);
    cudaGetSymbolAddress(&p_aoh, g_ao_h);

    cudaFuncSetAttribute(flash_mma, cudaFuncAttributeMaxDynamicSharedMemorySize, FL_SMEM);
    cudaFuncSetAttribute(gemm_mma<0>, cudaFuncAttributeMaxDynamicSharedMemorySize, GEMM_SMEM);
    cudaFuncSetAttribute(gemm_mma<1>, cudaFuncAttributeMaxDynamicSharedMemorySize, GEMM_SMEM);

    decay_kernel<<<(HH * TT + 255) / 256, 256>>>(lambda_raw);
    conv3<<<CN3 / 256, 256>>>(x, qkv_w, proj_w);

    gemm_mma<0><<<dim3(3072 / 128, 4096 / 256), 256, GEMM_SMEM>>>(
        (const __half*)p_xh, (const __half*)p_w1h, qkv_b, nullptr, 3072);

    sumv_kernel<<<dim3(BB * HH, 8), 256>>>();

    flash_mma<<<dim3(TT / 128, BB * HH), 256, FL_SMEM>>>();

    gemm_mma<1><<<dim3(1024 / 128, 4096 / 256), 256, GEMM_SMEM>>>(
        (const __half*)p_aoh, (const __half*)p_w2h, proj_b, out, 1024);
}

// round 16
// speedup vs baseline: 3.9692x; 1.0191x over previous
#include <cuda_runtime.h>
#include <cuda_fp16.h>
#include <math.h>
#include <stdint.h>

#define BB 2
#define TT 2048
#define CC 1024
#define HH 16
#define DH 64

// ---------------------------------------------------------------------------
__device__ float g_decay[HH * TT];                 // [h][dist]
__device__ int   g_cut[HH];                        // near-field cutoff per head
__device__ float g_sv[BB * HH * DH];               // column sums of V (fp32)

__device__ __half g_q_h[4194304];                  // [b][h][t][d]
__device__ __half g_k_h[4194304];
__device__ __half g_v_h[4194304];
__device__ __half g_ao_h[4194304];

__device__ __half g_x_h[4194304];
__device__ __half g_w1_h[3145728];
__device__ __half g_w2_h[1048576];

// ---------------------------------------------------------------------------
__device__ __forceinline__ uint32_t smem_u32(const void* p) {
    uint32_t a;
    asm("{ .reg .u64 t; cvta.to.shared.u64 t, %1; cvt.u32.u64 %0, t; }" : "=r"(a) : "l"(p));
    return a;
}
__device__ __forceinline__ uint32_t swz(uint32_t off) {
    return off ^ ((off >> 3) & 0x70);
}
__device__ __forceinline__ void ldmx4(uint32_t* r, uint32_t addr) {
    asm volatile("ldmatrix.sync.aligned.m8n8.x4.shared.b16 {%0,%1,%2,%3}, [%4];"
                 : "=r"(r[0]), "=r"(r[1]), "=r"(r[2]), "=r"(r[3]) : "r"(addr));
}
__device__ __forceinline__ void ldmx4t(uint32_t* r, uint32_t addr) {
    asm volatile("ldmatrix.sync.aligned.m8n8.x4.trans.shared.b16 {%0,%1,%2,%3}, [%4];"
                 : "=r"(r[0]), "=r"(r[1]), "=r"(r[2]), "=r"(r[3]) : "r"(addr));
}
__device__ __forceinline__ void mma_f16(float* c, const uint32_t* a, uint32_t b0, uint32_t b1) {
    asm volatile("mma.sync.aligned.m16n8k16.row.col.f32.f16.f16.f32 "
                 "{%0,%1,%2,%3}, {%4,%5,%6,%7}, {%8,%9}, {%0,%1,%2,%3};"
                 : "+f"(c[0]), "+f"(c[1]), "+f"(c[2]), "+f"(c[3])
                 : "r"(a[0]), "r"(a[1]), "r"(a[2]), "r"(a[3]), "r"(b0), "r"(b1));
}
__device__ __forceinline__ void cpa16(uint32_t dst, const void* src) {
    asm volatile("cp.async.cg.shared.global [%0], [%1], 16;" :: "r"(dst), "l"(src));
}
#define CP_COMMIT() asm volatile("cp.async.commit_group;" ::: "memory")
#define CP_WAIT1()  asm volatile("cp.async.wait_group 1;" ::: "memory")
#define CP_WAIT0()  asm volatile("cp.async.wait_group 0;" ::: "memory")

__device__ __forceinline__ float fexp2(float y) {
    y = fminf(fmaxf(y, -120.f), 80.f);
    float z = y + 12582912.f;
    int iz = __float_as_int(z);
    float f = y - (z - 12582912.f);
    float p = 1.3333558e-3f;
    p = fmaf(p, f, 9.6181291e-3f);
    p = fmaf(p, f, 5.5504109e-2f);
    p = fmaf(p, f, 2.4022651e-1f);
    p = fmaf(p, f, 6.9314718e-1f);
    p = fmaf(p, f, 1.0f);
    return p * __int_as_float((iz + (127 - 0x4B400000)) << 23);
}
__device__ __forceinline__ uint32_t pack16(float x, float y) {
    __half hx = __float2half_rn(x), hy = __float2half_rn(y);
    return ((uint32_t)__half_as_ushort(hy) << 16) | (uint32_t)__half_as_ushort(hx);
}

// ---------------------------------------------------------------------------
// one fused conversion kernel for x, qkv_w, proj_w
// ---------------------------------------------------------------------------
#define CN1 1048576                    // x float4 count
#define CN2 (CN1 + 786432)             // + w1
#define CN3 (CN2 + 262144)             // + w2
__global__ void conv3(const float* __restrict__ x, const float* __restrict__ w1,
                      const float* __restrict__ w2) {
    int i = blockIdx.x * blockDim.x + threadIdx.x;
    const float* src;
    __half* dst;
    int off;
    if (i < CN1)      { src = x;  dst = g_x_h;  off = i; }
    else if (i < CN2) { src = w1; dst = g_w1_h; off = i - CN1; }
    else if (i < CN3) { src = w2; dst = g_w2_h; off = i - CN2; }
    else return;
    float4 v = ((const float4*)src)[off];
    __half2* H = (__half2*)dst;
    H[off * 2]     = __half2(__float2half_rn(v.x), __float2half_rn(v.y));
    H[off * 2 + 1] = __half2(__float2half_rn(v.z), __float2half_rn(v.w));
}

// decay table + analytic cutoff + zero g_sv
__global__ void decay_kernel(const float* __restrict__ lambda_raw) {
    int idx = blockIdx.x * blockDim.x + threadIdx.x;
    if (idx < BB * HH * DH) g_sv[idx] = 0.f;
    if (idx < HH * TT) {
        int h = idx / TT;
        int d = idx % TT;
        float lam = log1pf(expf(lambda_raw[h]));
        g_decay[idx] = expf(-lam * (float)d);
        if (d == 0) {
            int cut = (int)ceilf(11.512925f / lam) + 1;   // ln(1e5)/lam
            g_cut[h] = (cut > TT) ? TT : cut;
        }
    }
}

// ---------------------------------------------------------------------------
// async tile loaders
// ---------------------------------------------------------------------------
__device__ __forceinline__ void gload_a256(const __half* __restrict__ g,
                                           uint32_t dst, int tid) {
#pragma unroll
    for (int i = 0; i < 8; i++) {
        int slot = tid + i * 256;
        int row = slot >> 3;
        int c16 = slot & 7;
        cpa16(dst + swz(row * 128 + c16 * 16), g + (size_t)row * 1024 + c16 * 8);
    }
}
__device__ __forceinline__ void gload_b128(const __half* __restrict__ g,
                                           uint32_t dst, int tid) {
#pragma unroll
    for (int i = 0; i < 4; i++) {
        int slot = tid + i * 256;
        int row = slot >> 3;
        int c16 = slot & 7;
        cpa16(dst + swz(row * 128 + c16 * 16), g + (size_t)row * 1024 + c16 * 8);
    }
}
__device__ __forceinline__ void gload_q128(const __half* __restrict__ g,
                                           uint32_t dst, int tid) {
#pragma unroll
    for (int i = 0; i < 4; i++) {
        int slot = tid + i * 256;
        int row = slot >> 3;
        int c16 = slot & 7;
        cpa16(dst + swz(row * 128 + c16 * 16), g + (size_t)row * 64 + c16 * 8);
    }
}
__device__ __forceinline__ void gload_kv64(const __half* __restrict__ g,
                                           uint32_t dst, int tid) {
#pragma unroll
    for (int i = 0; i < 2; i++) {
        int slot = tid + i * 256;
        int row = slot >> 3;
        int c16 = slot & 7;
        cpa16(dst + swz(row * 128 + c16 * 16), g + (size_t)row * 64 + c16 * 8);
    }
}

// ---------------------------------------------------------------------------
// fp16 mma.sync NT GEMM. EPI 0 additionally accumulates V column sums
// (fp32, pre-quantization) into g_sv from the V-region CTAs.
// ---------------------------------------------------------------------------
#define GA_H 0
#define GB_H 32768
#define GBUF 49152
#define GEMM_SMEM 98304

template <int EPI>
__launch_bounds__(256, 1)
__global__ void gemm_mma(const __half* __restrict__ Ah, const __half* __restrict__ Bh,
                         const float* __restrict__ bias, float* __restrict__ Cout, int N) {
    extern __shared__ char smem[];
    const uint32_t sb = smem_u32(smem);
    const int tid = threadIdx.x;
    const int wid = tid >> 5;
    const int lane = tid & 31;
    const int wm = wid & 3;
    const int wn = wid >> 2;
    const int n0 = blockIdx.x * 128;
    const int m0 = blockIdx.y * 256;

    const int a_row = (lane & 7) + ((lane >> 3) & 1) * 8;
    const int a_kc  = lane >> 4;
    const int b_row = ((lane >> 4) * 8) + (lane & 7);
    const int b_kc  = (lane >> 3) & 1;

    const __half* Abase = Ah + (size_t)m0 * 1024;
    const __half* Bbase = Bh + (size_t)n0 * 1024;

    float acc[4][8][4];
#pragma unroll
    for (int i = 0; i < 4; i++)
#pragma unroll
        for (int j = 0; j < 8; j++)
#pragma unroll
            for (int q = 0; q < 4; q++) acc[i][j][q] = 0.f;

    gload_a256(Abase, sb + GA_H, tid);
    gload_b128(Bbase, sb + GB_H, tid);
    CP_COMMIT();

    for (int c = 0; c < 16; c++) {
        const uint32_t cur = (c & 1) ? GBUF : 0u;
        const uint32_t nxt = cur ^ GBUF;
        if (c < 15) {
            const size_t ka = (size_t)(c + 1) * 64;
            gload_a256(Abase + ka, sb + nxt + GA_H, tid);
            gload_b128(Bbase + ka, sb + nxt + GB_H, tid);
            CP_COMMIT();
            CP_WAIT1();
        } else {
            CP_WAIT0();
        }
        __syncthreads();

        const uint32_t sAh = sb + cur + GA_H;
        const uint32_t sBh = sb + cur + GB_H;
#pragma unroll
        for (int kt = 0; kt < 4; kt++) {
            uint32_t ah[4][4];
#pragma unroll
            for (int mi = 0; mi < 4; mi++) {
                uint32_t off = swz((wm * 64 + mi * 16 + a_row) * 128 + (kt * 2 + a_kc) * 16);
                ldmx4(ah[mi], sAh + off);
            }
#pragma unroll
            for (int ng = 0; ng < 4; ng++) {
                uint32_t bh[4];
                uint32_t off = swz((wn * 64 + ng * 16 + b_row) * 128 + (kt * 2 + b_kc) * 16);
                ldmx4(bh, sBh + off);
#pragma unroll
                for (int mi = 0; mi < 4; mi++) {
                    mma_f16(acc[mi][2 * ng],     ah[mi], bh[0], bh[1]);
                    mma_f16(acc[mi][2 * ng + 1], ah[mi], bh[2], bh[3]);
                }
            }
        }
        __syncthreads();
    }

    // epilogue
    const int s_cta = n0 >> 10;               // constant per CTA (n0 128-aligned)
    float svx[8], svy[8];
    if (EPI == 0 && s_cta == 2) {
#pragma unroll
        for (int j = 0; j < 8; j++) { svx[j] = 0.f; svy[j] = 0.f; }
    }

#pragma unroll
    for (int mi = 0; mi < 4; mi++) {
#pragma unroll
        for (int j = 0; j < 8; j++) {
            int row = m0 + wm * 64 + mi * 16 + (lane >> 2);
            int o = n0 + wn * 64 + j * 8 + (lane & 3) * 2;
            float b0 = bias[o], b1 = bias[o + 1];
#pragma unroll
            for (int half = 0; half < 2; half++) {
                int m = row + half * 8;
                float vx = acc[mi][j][half * 2] + b0;
                float vy = acc[mi][j][half * 2 + 1] + b1;
                if (EPI == 0) {
                    int rem = o & 1023;
                    int hh = rem >> 6;
                    int d = rem & 63;
                    int bb = m >> 11;
                    int t = m & 2047;
                    size_t idx = (((size_t)(bb * HH + hh) * TT + t) * DH + d) >> 1;
                    __half2 hv(__float2half_rn(vx), __float2half_rn(vy));
                    if (s_cta == 0)      ((__half2*)g_q_h)[idx] = hv;
                    else if (s_cta == 1) ((__half2*)g_k_h)[idx] = hv;
                    else {
                        ((__half2*)g_v_h)[idx] = hv;
                        svx[j] += vx;
                        svy[j] += vy;
                    }
                } else {
                    *(float2*)&Cout[(size_t)m * N + o] = make_float2(vx, vy);
                }
            }
        }
    }

    if (EPI == 0 && s_cta == 2) {
        // reduce across the 8 row-lanes (lane>>2) of each quad-column group
#pragma unroll
        for (int j = 0; j < 8; j++) {
#pragma unroll
            for (int msk = 4; msk < 32; msk <<= 1) {
                svx[j] += __shfl_xor_sync(0xffffffffu, svx[j], msk);
                svy[j] += __shfl_xor_sync(0xffffffffu, svy[j], msk);
            }
        }
        if (lane < 4) {
            const int o0 = n0 + wn * 64 + lane * 2;
            const int hh = (o0 & 1023) >> 6;
            const int bb = m0 >> 11;
            float* svp = g_sv + (size_t)(bb * HH + hh) * DH;
#pragma unroll
            for (int j = 0; j < 8; j++) {
                atomicAdd(&svp[j * 8 + lane * 2],     svx[j]);
                atomicAdd(&svp[j * 8 + lane * 2 + 1], svy[j]);
            }
        }
    }
}

// ---------------------------------------------------------------------------
// Flash attention, far-field factorized, 128 q-rows/CTA (unchanged)
// ---------------------------------------------------------------------------
#define FQ_H  0
#define FBUF0 16384
#define FBSZ  16384
#define F_KH  0
#define F_VH  8192
#define FL_SMEM 49152

__launch_bounds__(256, 2)
__global__ void flash_mma() {
    extern __shared__ char fsm[];
    const uint32_t sb = smem_u32(fsm);
    const int tid = threadIdx.x;
    const int wid = tid >> 5;
    const int lane = tid & 31;
    const int b = blockIdx.y >> 4;
    const int h = blockIdx.y & 15;
    const int i0 = blockIdx.x * 128;

    const int a_row = (lane & 7) + ((lane >> 3) & 1) * 8;
    const int a_kc  = lane >> 4;
    const int b_row = ((lane >> 4) * 8) + (lane & 7);
    const int b_kc  = (lane >> 3) & 1;
    const int v_row = (lane & 7) + ((lane >> 3) & 1) * 8;
    const int v_dc  = (lane >> 4) * 8;

    const size_t qoff = (size_t)(b * HH + h) * TT * DH;
    const __half* Qh = g_q_h + qoff + (size_t)i0 * DH;
    const __half* Kh = g_k_h + qoff;
    const __half* Vh = g_v_h + qoff;
    const float* dec = g_decay + h * TT;

    const int cut = g_cut[h];
    int c_lo = i0 - cut;
    c_lo = (c_lo < 0) ? 0 : (c_lo >> 6);
    int c_hi = ((i0 + 127 + cut) >> 6) + 1;
    if (c_hi > TT / 64) c_hi = TT / 64;

    gload_q128(Qh, sb + FQ_H, tid);
    CP_COMMIT();
    {
        const uint32_t d0 = sb + FBUF0 + (c_lo & 1) * FBSZ;
        gload_kv64(Kh + (size_t)c_lo * 64 * DH, d0 + F_KH, tid);
        gload_kv64(Vh + (size_t)c_lo * 64 * DH, d0 + F_VH, tid);
        CP_COMMIT();
    }
    CP_WAIT1();
    __syncthreads();

    uint32_t qh[4][4];
#pragma unroll
    for (int kt = 0; kt < 4; kt++) {
        uint32_t off = swz((wid * 16 + a_row) * 128 + (kt * 2 + a_kc) * 16);
        ldmx4(qh[kt], sb + FQ_H + off);
    }

    float O[8][4];
#pragma unroll
    for (int j = 0; j < 8; j++)
#pragma unroll
        for (int q = 0; q < 4; q++) O[j][q] = 0.f;
    float lsum0 = 0.f, lsum1 = 0.f;
    const float K1 = 0.125f * 1.44269504f;
    const int r_lo = i0 + wid * 16 + (lane >> 2);

    for (int c = c_lo; c < c_hi; c++) {
        CP_WAIT0();
        __syncthreads();

        if (c + 1 < c_hi) {
            const uint32_t dn = sb + FBUF0 + ((c + 1) & 1) * FBSZ;
            const size_t j1 = (size_t)(c + 1) * 64;
            gload_kv64(Kh + j1 * DH, dn + F_KH, tid);
            gload_kv64(Vh + j1 * DH, dn + F_VH, tid);
            CP_COMMIT();
        }

        const uint32_t cur = sb + FBUF0 + (c & 1) * FBSZ;
        const uint32_t sKh = cur + F_KH;
        const uint32_t sVh = cur + F_VH;
        const int j0 = c * 64;

        float s[8][4];
#pragma unroll
        for (int j = 0; j < 8; j++)
#pragma unroll
            for (int q = 0; q < 4; q++) s[j][q] = 0.f;
#pragma unroll
        for (int kt = 0; kt < 4; kt++) {
#pragma unroll
            for (int ng = 0; ng < 4; ng++) {
                uint32_t kb[4];
                uint32_t off = swz((ng * 16 + b_row) * 128 + (kt * 2 + b_kc) * 16);
                ldmx4(kb, sKh + off);
                mma_f16(s[2 * ng],     qh[kt], kb[0], kb[1]);
                mma_f16(s[2 * ng + 1], qh[kt], kb[2], kb[3]);
            }
        }

#pragma unroll
        for (int j = 0; j < 8; j++) {
            int cbase = j0 + j * 8 + (lane & 3) * 2;
#pragma unroll
            for (int cc = 0; cc < 4; cc++) {
                int rg = r_lo + ((cc >= 2) ? 8 : 0);
                int cg = cbase + (cc & 1);
                float dcy = __ldg(&dec[abs(rg - cg)]);
                float pm1 = fexp2(s[j][cc] * dcy * K1) - 1.0f;
                s[j][cc] = pm1;
                if (cc < 2) lsum0 += pm1; else lsum1 += pm1;
            }
        }

#pragma unroll
        for (int kt = 0; kt < 4; kt++) {
            uint32_t ph[4];
            ph[0] = pack16(s[2 * kt][0],     s[2 * kt][1]);
            ph[1] = pack16(s[2 * kt][2],     s[2 * kt][3]);
            ph[2] = pack16(s[2 * kt + 1][0], s[2 * kt + 1][1]);
            ph[3] = pack16(s[2 * kt + 1][2], s[2 * kt + 1][3]);
#pragma unroll
            for (int ng = 0; ng < 4; ng++) {
                uint32_t vh2[4];
                uint32_t off = swz((kt * 16 + v_row) * 128 + (ng * 16 + v_dc) * 2);
                ldmx4t(vh2, sVh + off);
                mma_f16(O[2 * ng],     ph, vh2[0], vh2[1]);
                mma_f16(O[2 * ng + 1], ph, vh2[2], vh2[3]);
            }
        }
    }

    const float* SVp = g_sv + (size_t)(b * HH + h) * DH;
    lsum0 += __shfl_xor_sync(0xffffffffu, lsum0, 1);
    lsum0 += __shfl_xor_sync(0xffffffffu, lsum0, 2);
    lsum1 += __shfl_xor_sync(0xffffffffu, lsum1, 1);
    lsum1 += __shfl_xor_sync(0xffffffffu, lsum1, 2);
    const float inv0 = 1.f / ((float)TT + lsum0);
    const float inv1 = 1.f / ((float)TT + lsum1);

#pragma unroll
    for (int j = 0; j < 8; j++) {
        int d = j * 8 + (lane & 3) * 2;
        float2 sv = *(const float2*)&SVp[d];
        size_t base0 = ((size_t)b * TT + (size_t)r_lo) * CC + h * DH + d;
        size_t base1 = base0 + 8 * CC;
        ((uint32_t*)g_ao_h)[base0 >> 1] =
            pack16((O[j][0] + sv.x) * inv0, (O[j][1] + sv.y) * inv0);
        ((uint32_t*)g_ao_h)[base1 >> 1] =
            pack16((O[j][2] + sv.x) * inv1, (O[j][3] + sv.y) * inv1);
    }
}

// ---------------------------------------------------------------------------
extern "C" void kernel_launch(void* const* d_in, const int* in_sizes, int n_in,
                              void* d_out, int out_size) {
    const float* x = (const float*)d_in[0];
    const float* qkv_w = (const float*)d_in[1];
    const float* qkv_b = (const float*)d_in[2];
    const float* proj_w = (const float*)d_in[3];
    const float* proj_b = (const float*)d_in[4];
    const float* lambda_raw = (const float*)d_in[5];
    float* out = (float*)d_out;

    void *p_xh, *p_w1h, *p_w2h, *p_aoh;
    cudaGetSymbolAddress(&p_xh, g_x_h);
    cudaGetSymbolAddress(&p_w1h, g_w1_h);
    cudaGetSymbolAddress(&p_w2h, g_w2_h);
    cudaGetSymbolAddress(&p_aoh, g_ao_h);

    cudaFuncSetAttribute(flash_mma, cudaFuncAttributeMaxDynamicSharedMemorySize, FL_SMEM);
    cudaFuncSetAttribute(gemm_mma<0>, cudaFuncAttributeMaxDynamicSharedMemorySize, GEMM_SMEM);
    cudaFuncSetAttribute(gemm_mma<1>, cudaFuncAttributeMaxDynamicSharedMemorySize, GEMM_SMEM);

    decay_kernel<<<(HH * TT + 255) / 256, 256>>>(lambda_raw);
    conv3<<<CN3 / 256, 256>>>(x, qkv_w, proj_w);

    gemm_mma<0><<<dim3(3072 / 128, 4096 / 256), 256, GEMM_SMEM>>>(
        (const __half*)p_xh, (const __half*)p_w1h, qkv_b, nullptr, 3072);

    flash_mma<<<dim3(TT / 128, BB * HH), 256, FL_SMEM>>>();

    gemm_mma<1><<<dim3(1024 / 128, 4096 / 256), 256, GEMM_SMEM>>>(
        (const __half*)p_aoh, (const __half*)p_w2h, proj_b, out, 1024);
}

// round 17
// speedup vs baseline: 4.0258x; 1.0142x over previous
#include <cuda_runtime.h>
#include <cuda_fp16.h>
#include <math.h>
#include <stdint.h>

#define BB 2
#define TT 2048
#define CC 1024
#define HH 16
#define DH 64

// ---------------------------------------------------------------------------
__device__ float g_decay[HH * TT];                 // [h][dist]
__device__ int   g_cut[HH];                        // near-field cutoff per head
__device__ float g_sv[BB * HH * DH];               // column sums of V (fp32)

__device__ __half g_q_h[4194304];                  // [b][h][t][d]
__device__ __half g_k_h[4194304];
__device__ __half g_v_h[4194304];
__device__ __half g_ao_h[4194304];

__device__ __half g_x_h[4194304];
__device__ __half g_w1_h[3145728];
__device__ __half g_w2_h[1048576];

// ---------------------------------------------------------------------------
__device__ __forceinline__ uint32_t smem_u32(const void* p) {
    uint32_t a;
    asm("{ .reg .u64 t; cvta.to.shared.u64 t, %1; cvt.u32.u64 %0, t; }" : "=r"(a) : "l"(p));
    return a;
}
__device__ __forceinline__ uint32_t swz(uint32_t off) {
    return off ^ ((off >> 3) & 0x70);
}
__device__ __forceinline__ void ldmx4(uint32_t* r, uint32_t addr) {
    asm volatile("ldmatrix.sync.aligned.m8n8.x4.shared.b16 {%0,%1,%2,%3}, [%4];"
                 : "=r"(r[0]), "=r"(r[1]), "=r"(r[2]), "=r"(r[3]) : "r"(addr));
}
__device__ __forceinline__ void ldmx4t(uint32_t* r, uint32_t addr) {
    asm volatile("ldmatrix.sync.aligned.m8n8.x4.trans.shared.b16 {%0,%1,%2,%3}, [%4];"
                 : "=r"(r[0]), "=r"(r[1]), "=r"(r[2]), "=r"(r[3]) : "r"(addr));
}
__device__ __forceinline__ void mma_f16(float* c, const uint32_t* a, uint32_t b0, uint32_t b1) {
    asm volatile("mma.sync.aligned.m16n8k16.row.col.f32.f16.f16.f32 "
                 "{%0,%1,%2,%3}, {%4,%5,%6,%7}, {%8,%9}, {%0,%1,%2,%3};"
                 : "+f"(c[0]), "+f"(c[1]), "+f"(c[2]), "+f"(c[3])
                 : "r"(a[0]), "r"(a[1]), "r"(a[2]), "r"(a[3]), "r"(b0), "r"(b1));
}
__device__ __forceinline__ void cpa16(uint32_t dst, const void* src) {
    asm volatile("cp.async.cg.shared.global [%0], [%1], 16;" :: "r"(dst), "l"(src));
}
#define CP_COMMIT() asm volatile("cp.async.commit_group;" ::: "memory")
#define CP_WAIT1()  asm volatile("cp.async.wait_group 1;" ::: "memory")
#define CP_WAIT0()  asm volatile("cp.async.wait_group 0;" ::: "memory")

__device__ __forceinline__ float fexp2(float y) {
    y = fminf(fmaxf(y, -120.f), 80.f);
    float z = y + 12582912.f;
    int iz = __float_as_int(z);
    float f = y - (z - 12582912.f);
    float p = 1.3333558e-3f;
    p = fmaf(p, f, 9.6181291e-3f);
    p = fmaf(p, f, 5.5504109e-2f);
    p = fmaf(p, f, 2.4022651e-1f);
    p = fmaf(p, f, 6.9314718e-1f);
    p = fmaf(p, f, 1.0f);
    return p * __int_as_float((iz + (127 - 0x4B400000)) << 23);
}
// one-instruction pack: lo = f16(x), hi = f16(y), round-to-nearest
__device__ __forceinline__ uint32_t pack16(float x, float y) {
    uint32_t r;
    asm("cvt.rn.f16x2.f32 %0, %1, %2;" : "=r"(r) : "f"(y), "f"(x));
    return r;
}

// ---------------------------------------------------------------------------
// one fused conversion kernel for x, qkv_w, proj_w
// ---------------------------------------------------------------------------
#define CN1 1048576                    // x float4 count
#define CN2 (CN1 + 786432)             // + w1
#define CN3 (CN2 + 262144)             // + w2
__global__ void conv3(const float* __restrict__ x, const float* __restrict__ w1,
                      const float* __restrict__ w2) {
    int i = blockIdx.x * blockDim.x + threadIdx.x;
    const float* src;
    __half* dst;
    int off;
    if (i < CN1)      { src = x;  dst = g_x_h;  off = i; }
    else if (i < CN2) { src = w1; dst = g_w1_h; off = i - CN1; }
    else if (i < CN3) { src = w2; dst = g_w2_h; off = i - CN2; }
    else return;
    float4 v = ((const float4*)src)[off];
    uint32_t* H = (uint32_t*)dst;
    H[off * 2]     = pack16(v.x, v.y);
    H[off * 2 + 1] = pack16(v.z, v.w);
}

// decay table + analytic cutoff + zero g_sv
__global__ void decay_kernel(const float* __restrict__ lambda_raw) {
    int idx = blockIdx.x * blockDim.x + threadIdx.x;
    if (idx < BB * HH * DH) g_sv[idx] = 0.f;
    if (idx < HH * TT) {
        int h = idx / TT;
        int d = idx % TT;
        float lam = log1pf(expf(lambda_raw[h]));
        g_decay[idx] = expf(-lam * (float)d);
        if (d == 0) {
            int cut = (int)ceilf(11.512925f / lam) + 1;   // ln(1e5)/lam
            g_cut[h] = (cut > TT) ? TT : cut;
        }
    }
}

// ---------------------------------------------------------------------------
// async tile loaders
// ---------------------------------------------------------------------------
__device__ __forceinline__ void gload_a256(const __half* __restrict__ g,
                                           uint32_t dst, int tid) {
#pragma unroll
    for (int i = 0; i < 8; i++) {
        int slot = tid + i * 256;
        int row = slot >> 3;
        int c16 = slot & 7;
        cpa16(dst + swz(row * 128 + c16 * 16), g + (size_t)row * 1024 + c16 * 8);
    }
}
__device__ __forceinline__ void gload_b128(const __half* __restrict__ g,
                                           uint32_t dst, int tid) {
#pragma unroll
    for (int i = 0; i < 4; i++) {
        int slot = tid + i * 256;
        int row = slot >> 3;
        int c16 = slot & 7;
        cpa16(dst + swz(row * 128 + c16 * 16), g + (size_t)row * 1024 + c16 * 8);
    }
}
__device__ __forceinline__ void gload_q128(const __half* __restrict__ g,
                                           uint32_t dst, int tid) {
#pragma unroll
    for (int i = 0; i < 4; i++) {
        int slot = tid + i * 256;
        int row = slot >> 3;
        int c16 = slot & 7;
        cpa16(dst + swz(row * 128 + c16 * 16), g + (size_t)row * 64 + c16 * 8);
    }
}
__device__ __forceinline__ void gload_kv64(const __half* __restrict__ g,
                                           uint32_t dst, int tid) {
#pragma unroll
    for (int i = 0; i < 2; i++) {
        int slot = tid + i * 256;
        int row = slot >> 3;
        int c16 = slot & 7;
        cpa16(dst + swz(row * 128 + c16 * 16), g + (size_t)row * 64 + c16 * 8);
    }
}

// ---------------------------------------------------------------------------
// fp16 mma.sync NT GEMM. EPI 0 additionally accumulates V column sums.
// ---------------------------------------------------------------------------
#define GA_H 0
#define GB_H 32768
#define GBUF 49152
#define GEMM_SMEM 98304

template <int EPI>
__launch_bounds__(256, 1)
__global__ void gemm_mma(const __half* __restrict__ Ah, const __half* __restrict__ Bh,
                         const float* __restrict__ bias, float* __restrict__ Cout, int N) {
    extern __shared__ char smem[];
    const uint32_t sb = smem_u32(smem);
    const int tid = threadIdx.x;
    const int wid = tid >> 5;
    const int lane = tid & 31;
    const int wm = wid & 3;
    const int wn = wid >> 2;
    const int n0 = blockIdx.x * 128;
    const int m0 = blockIdx.y * 256;

    const int a_row = (lane & 7) + ((lane >> 3) & 1) * 8;
    const int a_kc  = lane >> 4;
    const int b_row = ((lane >> 4) * 8) + (lane & 7);
    const int b_kc  = (lane >> 3) & 1;

    const __half* Abase = Ah + (size_t)m0 * 1024;
    const __half* Bbase = Bh + (size_t)n0 * 1024;

    float acc[4][8][4];
#pragma unroll
    for (int i = 0; i < 4; i++)
#pragma unroll
        for (int j = 0; j < 8; j++)
#pragma unroll
            for (int q = 0; q < 4; q++) acc[i][j][q] = 0.f;

    gload_a256(Abase, sb + GA_H, tid);
    gload_b128(Bbase, sb + GB_H, tid);
    CP_COMMIT();

    for (int c = 0; c < 16; c++) {
        const uint32_t cur = (c & 1) ? GBUF : 0u;
        const uint32_t nxt = cur ^ GBUF;
        if (c < 15) {
            const size_t ka = (size_t)(c + 1) * 64;
            gload_a256(Abase + ka, sb + nxt + GA_H, tid);
            gload_b128(Bbase + ka, sb + nxt + GB_H, tid);
            CP_COMMIT();
            CP_WAIT1();
        } else {
            CP_WAIT0();
        }
        __syncthreads();

        const uint32_t sAh = sb + cur + GA_H;
        const uint32_t sBh = sb + cur + GB_H;
#pragma unroll
        for (int kt = 0; kt < 4; kt++) {
            uint32_t ah[4][4];
#pragma unroll
            for (int mi = 0; mi < 4; mi++) {
                uint32_t off = swz((wm * 64 + mi * 16 + a_row) * 128 + (kt * 2 + a_kc) * 16);
                ldmx4(ah[mi], sAh + off);
            }
#pragma unroll
            for (int ng = 0; ng < 4; ng++) {
                uint32_t bh[4];
                uint32_t off = swz((wn * 64 + ng * 16 + b_row) * 128 + (kt * 2 + b_kc) * 16);
                ldmx4(bh, sBh + off);
#pragma unroll
                for (int mi = 0; mi < 4; mi++) {
                    mma_f16(acc[mi][2 * ng],     ah[mi], bh[0], bh[1]);
                    mma_f16(acc[mi][2 * ng + 1], ah[mi], bh[2], bh[3]);
                }
            }
        }
        __syncthreads();
    }

    // epilogue
    const int s_cta = n0 >> 10;               // constant per CTA
    float svx[8], svy[8];
    if (EPI == 0 && s_cta == 2) {
#pragma unroll
        for (int j = 0; j < 8; j++) { svx[j] = 0.f; svy[j] = 0.f; }
    }

#pragma unroll
    for (int mi = 0; mi < 4; mi++) {
#pragma unroll
        for (int j = 0; j < 8; j++) {
            int row = m0 + wm * 64 + mi * 16 + (lane >> 2);
            int o = n0 + wn * 64 + j * 8 + (lane & 3) * 2;
            float b0 = bias[o], b1 = bias[o + 1];
#pragma unroll
            for (int half = 0; half < 2; half++) {
                int m = row + half * 8;
                float vx = acc[mi][j][half * 2] + b0;
                float vy = acc[mi][j][half * 2 + 1] + b1;
                if (EPI == 0) {
                    int rem = o & 1023;
                    int hh = rem >> 6;
                    int d = rem & 63;
                    int bb = m >> 11;
                    int t = m & 2047;
                    size_t idx = (((size_t)(bb * HH + hh) * TT + t) * DH + d) >> 1;
                    uint32_t hv = pack16(vx, vy);
                    if (s_cta == 0)      ((uint32_t*)g_q_h)[idx] = hv;
                    else if (s_cta == 1) ((uint32_t*)g_k_h)[idx] = hv;
                    else {
                        ((uint32_t*)g_v_h)[idx] = hv;
                        svx[j] += vx;
                        svy[j] += vy;
                    }
                } else {
                    *(float2*)&Cout[(size_t)m * N + o] = make_float2(vx, vy);
                }
            }
        }
    }

    if (EPI == 0 && s_cta == 2) {
#pragma unroll
        for (int j = 0; j < 8; j++) {
#pragma unroll
            for (int msk = 4; msk < 32; msk <<= 1) {
                svx[j] += __shfl_xor_sync(0xffffffffu, svx[j], msk);
                svy[j] += __shfl_xor_sync(0xffffffffu, svy[j], msk);
            }
        }
        if (lane < 4) {
            const int o0 = n0 + wn * 64 + lane * 2;
            const int hh = (o0 & 1023) >> 6;
            const int bb = m0 >> 11;
            float* svp = g_sv + (size_t)(bb * HH + hh) * DH;
#pragma unroll
            for (int j = 0; j < 8; j++) {
                atomicAdd(&svp[j * 8 + lane * 2],     svx[j]);
                atomicAdd(&svp[j * 8 + lane * 2 + 1], svy[j]);
            }
        }
    }
}

// ---------------------------------------------------------------------------
// Flash attention, far-field factorized, 128 q-rows/CTA.
// blockIdx.x remapped center-first (LPT scheduling over 2 waves).
// ---------------------------------------------------------------------------
#define FQ_H  0
#define FBUF0 16384
#define FBSZ  16384
#define F_KH  0
#define F_VH  8192
#define FL_SMEM 49152

__launch_bounds__(256, 2)
__global__ void flash_mma() {
    extern __shared__ char fsm[];
    const uint32_t sb = smem_u32(fsm);
    const int tid = threadIdx.x;
    const int wid = tid >> 5;
    const int lane = tid & 31;
    const int b = blockIdx.y >> 4;
    const int h = blockIdx.y & 15;
    // LPT remap: heavy (center) q-tiles first: 8,7,9,6,10,5,...
    const int bx = blockIdx.x;
    const int qi = (bx & 1) ? (7 - (bx >> 1)) : (8 + (bx >> 1));
    const int i0 = qi * 128;

    const int a_row = (lane & 7) + ((lane >> 3) & 1) * 8;
    const int a_kc  = lane >> 4;
    const int b_row = ((lane >> 4) * 8) + (lane & 7);
    const int b_kc  = (lane >> 3) & 1;
    const int v_row = (lane & 7) + ((lane >> 3) & 1) * 8;
    const int v_dc  = (lane >> 4) * 8;

    const size_t qoff = (size_t)(b * HH + h) * TT * DH;
    const __half* Qh = g_q_h + qoff + (size_t)i0 * DH;
    const __half* Kh = g_k_h + qoff;
    const __half* Vh = g_v_h + qoff;
    const float* dec = g_decay + h * TT;

    const int cut = g_cut[h];
    int c_lo = i0 - cut;
    c_lo = (c_lo < 0) ? 0 : (c_lo >> 6);
    int c_hi = ((i0 + 127 + cut) >> 6) + 1;
    if (c_hi > TT / 64) c_hi = TT / 64;

    gload_q128(Qh, sb + FQ_H, tid);
    CP_COMMIT();
    {
        const uint32_t d0 = sb + FBUF0 + (c_lo & 1) * FBSZ;
        gload_kv64(Kh + (size_t)c_lo * 64 * DH, d0 + F_KH, tid);
        gload_kv64(Vh + (size_t)c_lo * 64 * DH, d0 + F_VH, tid);
        CP_COMMIT();
    }
    CP_WAIT1();
    __syncthreads();

    uint32_t qh[4][4];
#pragma unroll
    for (int kt = 0; kt < 4; kt++) {
        uint32_t off = swz((wid * 16 + a_row) * 128 + (kt * 2 + a_kc) * 16);
        ldmx4(qh[kt], sb + FQ_H + off);
    }

    float O[8][4];
#pragma unroll
    for (int j = 0; j < 8; j++)
#pragma unroll
        for (int q = 0; q < 4; q++) O[j][q] = 0.f;
    float lsum0 = 0.f, lsum1 = 0.f;
    const float K1 = 0.125f * 1.44269504f;
    const int r_lo = i0 + wid * 16 + (lane >> 2);

    for (int c = c_lo; c < c_hi; c++) {
        CP_WAIT0();
        __syncthreads();

        if (c + 1 < c_hi) {
            const uint32_t dn = sb + FBUF0 + ((c + 1) & 1) * FBSZ;
            const size_t j1 = (size_t)(c + 1) * 64;
            gload_kv64(Kh + j1 * DH, dn + F_KH, tid);
            gload_kv64(Vh + j1 * DH, dn + F_VH, tid);
            CP_COMMIT();
        }

        const uint32_t cur = sb + FBUF0 + (c & 1) * FBSZ;
        const uint32_t sKh = cur + F_KH;
        const uint32_t sVh = cur + F_VH;
        const int j0 = c * 64;

        float s[8][4];
#pragma unroll
        for (int j = 0; j < 8; j++)
#pragma unroll
            for (int q = 0; q < 4; q++) s[j][q] = 0.f;
#pragma unroll
        for (int kt = 0; kt < 4; kt++) {
#pragma unroll
            for (int ng = 0; ng < 4; ng++) {
                uint32_t kb[4];
                uint32_t off = swz((ng * 16 + b_row) * 128 + (kt * 2 + b_kc) * 16);
                ldmx4(kb, sKh + off);
                mma_f16(s[2 * ng],     qh[kt], kb[0], kb[1]);
                mma_f16(s[2 * ng + 1], qh[kt], kb[2], kb[3]);
            }
        }

#pragma unroll
        for (int j = 0; j < 8; j++) {
            int cbase = j0 + j * 8 + (lane & 3) * 2;
#pragma unroll
            for (int cc = 0; cc < 4; cc++) {
                int rg = r_lo + ((cc >= 2) ? 8 : 0);
                int cg = cbase + (cc & 1);
                float dcy = __ldg(&dec[abs(rg - cg)]);
                float pm1 = fexp2(s[j][cc] * dcy * K1) - 1.0f;
                s[j][cc] = pm1;
                if (cc < 2) lsum0 += pm1; else lsum1 += pm1;
            }
        }

#pragma unroll
        for (int kt = 0; kt < 4; kt++) {
            uint32_t ph[4];
            ph[0] = pack16(s[2 * kt][0],     s[2 * kt][1]);
            ph[1] = pack16(s[2 * kt][2],     s[2 * kt][3]);
            ph[2] = pack16(s[2 * kt + 1][0], s[2 * kt + 1][1]);
            ph[3] = pack16(s[2 * kt + 1][2], s[2 * kt + 1][3]);
#pragma unroll
            for (int ng = 0; ng < 4; ng++) {
                uint32_t vh2[4];
                uint32_t off = swz((kt * 16 + v_row) * 128 + (ng * 16 + v_dc) * 2);
                ldmx4t(vh2, sVh + off);
                mma_f16(O[2 * ng],     ph, vh2[0], vh2[1]);
                mma_f16(O[2 * ng + 1], ph, vh2[2], vh2[3]);
            }
        }
    }

    const float* SVp = g_sv + (size_t)(b * HH + h) * DH;
    lsum0 += __shfl_xor_sync(0xffffffffu, lsum0, 1);
    lsum0 += __shfl_xor_sync(0xffffffffu, lsum0, 2);
    lsum1 += __shfl_xor_sync(0xffffffffu, lsum1, 1);
    lsum1 += __shfl_xor_sync(0xffffffffu, lsum1, 2);
    const float inv0 = 1.f / ((float)TT + lsum0);
    const float inv1 = 1.f / ((float)TT + lsum1);

#pragma unroll
    for (int j = 0; j < 8; j++) {
        int d = j * 8 + (lane & 3) * 2;
        float2 sv = *(const float2*)&SVp[d];
        size_t base0 = ((size_t)b * TT + (size_t)r_lo) * CC + h * DH + d;
        size_t base1 = base0 + 8 * CC;
        ((uint32_t*)g_ao_h)[base0 >> 1] =
            pack16((O[j][0] + sv.x) * inv0, (O[j][1] + sv.y) * inv0);
        ((uint32_t*)g_ao_h)[base1 >> 1] =
            pack16((O[j][2] + sv.x) * inv1, (O[j][3] + sv.y) * inv1);
    }
}

// ---------------------------------------------------------------------------
extern "C" void kernel_launch(void* const* d_in, const int* in_sizes, int n_in,
                              void* d_out, int out_size) {
    const float* x = (const float*)d_in[0];
    const float* qkv_w = (const float*)d_in[1];
    const float* qkv_b = (const float*)d_in[2];
    const float* proj_w = (const float*)d_in[3];
    const float* proj_b = (const float*)d_in[4];
    const float* lambda_raw = (const float*)d_in[5];
    float* out = (float*)d_out;

    void *p_xh, *p_w1h, *p_w2h, *p_aoh;
    cudaGetSymbolAddress(&p_xh, g_x_h);
    cudaGetSymbolAddress(&p_w1h, g_w1_h);
    cudaGetSymbolAddress(&p_w2h, g_w2_h);
    cudaGetSymbolAddress(&p_aoh, g_ao_h);

    cudaFuncSetAttribute(flash_mma, cudaFuncAttributeMaxDynamicSharedMemorySize, FL_SMEM);
    cudaFuncSetAttribute(gemm_mma<0>, cudaFuncAttributeMaxDynamicSharedMemorySize, GEMM_SMEM);
    cudaFuncSetAttribute(gemm_mma<1>, cudaFuncAttributeMaxDynamicSharedMemorySize, GEMM_SMEM);

    decay_kernel<<<(HH * TT + 255) / 256, 256>>>(lambda_raw);
    conv3<<<CN3 / 256, 256>>>(x, qkv_w, proj_w);

    gemm_mma<0><<<dim3(3072 / 128, 4096 / 256), 256, GEMM_SMEM>>>(
        (const __half*)p_xh, (const __half*)p_w1h, qkv_b, nullptr, 3072);

    flash_mma<<<dim3(TT / 128, BB * HH), 256, FL_SMEM>>>();

    gemm_mma<1><<<dim3(1024 / 128, 4096 / 256), 256, GEMM_SMEM>>>(
        (const __half*)p_aoh, (const __half*)p_w2h, proj_b, out, 1024);
}